// round 4
// baseline (speedup 1.0000x reference)
#include <cuda_runtime.h>
#include <math.h>

#define B_ 2
#define S_ 2048
#define D_ 1024
#define H_ 16
#define DEPTH_ 64
#define DFF_ 4096
#define NT_ (B_ * S_)
#define EPS_ 1e-5f
#define NROWS_ (B_ * H_ * S_)     // 65536 attention rows
#define NKT_ 16                   // S/128 k-tiles

// ---------------- scratch ----------------
__device__ float g_q  [NT_ * D_];
__device__ float g_k  [NT_ * D_];
__device__ float g_v  [NT_ * D_];
__device__ float g_ctx[NT_ * D_];
__device__ float g_ao [NT_ * D_];
__device__ float g_x1 [NT_ * D_];
__device__ float g_x1r[NT_ * D_];
__device__ float g_h1 [NT_ * DFF_];
__device__ float g_ff2[NT_ * D_];
__device__ float g_xr [NT_ * D_];
__device__ float g_wr [12582912];
__device__ float g_rs [NROWS_ * NKT_];   // partial row sums
__device__ float g_inv[NROWS_];          // 1/rowsum

// ---------------- helpers ----------------
__device__ __forceinline__ unsigned f2tf(float x) {
    unsigned r;
    asm("cvt.rna.tf32.f32 %0, %1;" : "=r"(r) : "f"(x));
    return r;
}
__device__ __forceinline__ float roundtf(float x) { return __uint_as_float(f2tf(x)); }

__device__ __forceinline__ void mma_tf32(float c[4],
                                         unsigned a0, unsigned a1, unsigned a2, unsigned a3,
                                         unsigned b0, unsigned b1) {
    asm volatile(
        "mma.sync.aligned.m16n8k8.row.col.f32.tf32.tf32.f32 "
        "{%0,%1,%2,%3},{%4,%5,%6,%7},{%8,%9},{%0,%1,%2,%3};\n"
        : "+f"(c[0]), "+f"(c[1]), "+f"(c[2]), "+f"(c[3])
        : "r"(a0), "r"(a1), "r"(a2), "r"(a3), "r"(b0), "r"(b1));
}

__device__ __forceinline__ void cp16(void* smem, const void* gmem) {
    unsigned sa = (unsigned)__cvta_generic_to_shared(smem);
    asm volatile("cp.async.cg.shared.global [%0], [%1], 16;\n" :: "r"(sa), "l"(gmem));
}
#define CP_COMMIT() asm volatile("cp.async.commit_group;\n" ::)
#define CP_WAIT1()  asm volatile("cp.async.wait_group 1;\n" ::)
#define CP_WAIT0()  asm volatile("cp.async.wait_group 0;\n" ::)

// ---------------- rna rounding pre-pass ----------------
__global__ void round_copy(const float* __restrict__ src, float* __restrict__ dst, int n4) {
    int i = blockIdx.x * 256 + threadIdx.x;
    if (i < n4) {
        float4 t = ((const float4*)src)[i];
        t.x = roundtf(t.x); t.y = roundtf(t.y); t.z = roundtf(t.z); t.w = roundtf(t.w);
        ((float4*)dst)[i] = t;
    }
}

// =====================================================================
// Dense GEMM, 3-stage cp.async pipeline, one sync per k-iter.
// Block 128x128, ktile 16, 8 warps (4m x 2n), warp tile 32x64.
// Dynamic smem: 3*(128*20 + 16*136) u32 = 56832 B.
// =====================================================================
#define ASZ_ 2560
#define BSZ_ 2176
template <int GELU, int ROUND>
__global__ __launch_bounds__(256, 2)
void gemm_tf32p(const float* __restrict__ A, const float* __restrict__ Bm,
                const float* __restrict__ bias, float* __restrict__ C,
                int M, int N, int K) {
    extern __shared__ unsigned dsm[];
    unsigned* Asp = dsm;              // [3][128][20]
    unsigned* Bsp = dsm + 3 * ASZ_;   // [3][16][136]

    const int tid = threadIdx.x;
    const int warp = tid >> 5, lane = tid & 31;
    const int g = lane >> 2, tg = lane & 3;
    const int m0 = blockIdx.y * 128, n0 = blockIdx.x * 128;
    const int wm = (warp >> 1) * 32, wn = (warp & 1) * 64;

    const int rA = tid >> 2,  kqA = (tid & 3) * 4;
    const int kB = tid >> 5,  nqB = (tid & 31) * 4;

    float c[2][8][4] = {};
    const int T = K >> 4;

    // prologue: stages 0 and 1
    #pragma unroll
    for (int s = 0; s < 2; s++) {
        const int k0 = s << 4;
        #pragma unroll
        for (int i = 0; i < 2; i++)
            cp16(&Asp[s * ASZ_ + (rA + i * 64) * 20 + kqA],
                 &A[(size_t)(m0 + rA + i * 64) * K + k0 + kqA]);
        #pragma unroll
        for (int i = 0; i < 2; i++)
            cp16(&Bsp[s * BSZ_ + (kB + i * 8) * 136 + nqB],
                 &Bm[(size_t)(k0 + kB + i * 8) * N + n0 + nqB]);
        CP_COMMIT();
    }

    for (int t = 0; t < T; t++) {
        if (t + 1 < T) CP_WAIT1(); else CP_WAIT0();
        __syncthreads();
        if (t + 2 < T) {
            const int s = (t + 2) % 3, k0 = (t + 2) << 4;
            #pragma unroll
            for (int i = 0; i < 2; i++)
                cp16(&Asp[s * ASZ_ + (rA + i * 64) * 20 + kqA],
                     &A[(size_t)(m0 + rA + i * 64) * K + k0 + kqA]);
            #pragma unroll
            for (int i = 0; i < 2; i++)
                cp16(&Bsp[s * BSZ_ + (kB + i * 8) * 136 + nqB],
                     &Bm[(size_t)(k0 + kB + i * 8) * N + n0 + nqB]);
            CP_COMMIT();
        }
        const unsigned* As = Asp + (t % 3) * ASZ_;
        const unsigned* Bs = Bsp + (t % 3) * BSZ_;
        #pragma unroll
        for (int ks = 0; ks < 16; ks += 8) {
            unsigned a[2][4], b[8][2];
            #pragma unroll
            for (int i = 0; i < 2; i++) {
                int mB = wm + i * 16;
                a[i][0] = As[(mB + g    ) * 20 + ks + tg    ];
                a[i][1] = As[(mB + g + 8) * 20 + ks + tg    ];
                a[i][2] = As[(mB + g    ) * 20 + ks + tg + 4];
                a[i][3] = As[(mB + g + 8) * 20 + ks + tg + 4];
            }
            #pragma unroll
            for (int j = 0; j < 8; j++) {
                int nB = wn + j * 8;
                b[j][0] = Bs[(ks + tg    ) * 136 + nB + g];
                b[j][1] = Bs[(ks + tg + 4) * 136 + nB + g];
            }
            #pragma unroll
            for (int i = 0; i < 2; i++)
                #pragma unroll
                for (int j = 0; j < 8; j++)
                    mma_tf32(c[i][j], a[i][0], a[i][1], a[i][2], a[i][3], b[j][0], b[j][1]);
        }
    }

    #pragma unroll
    for (int i = 0; i < 2; i++) {
        #pragma unroll
        for (int j = 0; j < 8; j++) {
            int col = n0 + wn + j * 8 + tg * 2;
            float b0v = bias[col], b1v = bias[col + 1];
            #pragma unroll
            for (int h = 0; h < 2; h++) {
                int row = m0 + wm + i * 16 + g + h * 8;
                float v0 = c[i][j][h * 2 + 0] + b0v;
                float v1 = c[i][j][h * 2 + 1] + b1v;
                if (GELU) {
                    v0 = 0.5f * v0 * (1.0f + erff(v0 * 0.70710678118654752f));
                    v1 = 0.5f * v1 * (1.0f + erff(v1 * 0.70710678118654752f));
                }
                if (ROUND) { v0 = roundtf(v0); v1 = roundtf(v1); }
                *(float2*)&C[(size_t)row * N + col] = make_float2(v0, v1);
            }
        }
    }
}

// =====================================================================
// Attention scores + exp + partial row sums.
// Writes P' = exp(QK/32) (masked on diagonal tile) to attn region, and
// per-(row, kt) partial sums to g_rs. Full Q/K tile load, no k-pipeline.
// Dynamic smem: 2*128*68 u32 = 69632 B.
// =====================================================================
__global__ __launch_bounds__(256, 2)
void attn_scores_exp(const float* __restrict__ Q, const float* __restrict__ Km,
                     float* __restrict__ attnP, float* __restrict__ rs) {
    const int kt = blockIdx.x, qt = blockIdx.y, bh = blockIdx.z;
    if (kt > qt) return;
    const int b = bh >> 4, h = bh & 15;

    extern __shared__ unsigned dsm[];
    unsigned* Qs = dsm;              // [128][68]
    unsigned* Ks = dsm + 128 * 68;   // [128][68]

    const int tid = threadIdx.x;
    const int warp = tid >> 5, lane = tid & 31;
    const int g = lane >> 2, tg = lane & 3;
    const int wm = (warp >> 1) * 32, wn = (warp & 1) * 64;

    const float* qb = Q  + (size_t)b * S_ * D_ + h * DEPTH_ + (size_t)(qt * 128) * D_;
    const float* kb = Km + (size_t)b * S_ * D_ + h * DEPTH_ + (size_t)(kt * 128) * D_;

    #pragma unroll
    for (int e = 0; e < 8; e++) {
        int u = tid + e * 256;            // 0..2047
        int r = u >> 4, cc = (u & 15) * 4;
        cp16(&Qs[r * 68 + cc], &qb[(size_t)r * D_ + cc]);
        cp16(&Ks[r * 68 + cc], &kb[(size_t)r * D_ + cc]);
    }
    CP_COMMIT();
    CP_WAIT0();
    __syncthreads();

    float c[2][8][4] = {};
    #pragma unroll
    for (int ks = 0; ks < 64; ks += 8) {
        unsigned a[2][4], bfr[8][2];
        #pragma unroll
        for (int i = 0; i < 2; i++) {
            int mB = wm + i * 16;
            a[i][0] = Qs[(mB + g    ) * 68 + ks + tg    ];
            a[i][1] = Qs[(mB + g + 8) * 68 + ks + tg    ];
            a[i][2] = Qs[(mB + g    ) * 68 + ks + tg + 4];
            a[i][3] = Qs[(mB + g + 8) * 68 + ks + tg + 4];
        }
        #pragma unroll
        for (int j = 0; j < 8; j++) {
            int nB = wn + j * 8;
            bfr[j][0] = Ks[(nB + g) * 68 + ks + tg    ];
            bfr[j][1] = Ks[(nB + g) * 68 + ks + tg + 4];
        }
        #pragma unroll
        for (int i = 0; i < 2; i++)
            #pragma unroll
            for (int j = 0; j < 8; j++)
                mma_tf32(c[i][j], a[i][0], a[i][1], a[i][2], a[i][3], bfr[j][0], bfr[j][1]);
    }

    // epilogue: scale, exp, causal mask (diagonal tile), write, partial sums
    const bool diag = (kt == qt);
    float rsum[2][2] = {};
    float* ob = attnP + ((size_t)bh * S_ + qt * 128) * S_ + kt * 128;
    #pragma unroll
    for (int i = 0; i < 2; i++)
        #pragma unroll
        for (int j = 0; j < 8; j++) {
            int col = wn + j * 8 + tg * 2;
            #pragma unroll
            for (int hh = 0; hh < 2; hh++) {
                int row = wm + i * 16 + g + hh * 8;
                float v0 = __expf(c[i][j][hh * 2 + 0] * 0.03125f);
                float v1 = __expf(c[i][j][hh * 2 + 1] * 0.03125f);
                if (diag) {
                    if (col     > row) v0 = 0.f;
                    if (col + 1 > row) v1 = 0.f;
                }
                rsum[i][hh] += v0 + v1;
                *(float2*)&ob[(size_t)row * S_ + col] = make_float2(v0, v1);
            }
        }

    // reduce partial sums across tg lanes, then across the 2 n-half warps
    #pragma unroll
    for (int i = 0; i < 2; i++)
        #pragma unroll
        for (int hh = 0; hh < 2; hh++) {
            rsum[i][hh] += __shfl_xor_sync(0xffffffff, rsum[i][hh], 1);
            rsum[i][hh] += __shfl_xor_sync(0xffffffff, rsum[i][hh], 2);
        }
    __syncthreads();                 // all MMA reads of Qs done -> reuse as [128][2]
    float* psm = (float*)Qs;
    if (tg == 0) {
        #pragma unroll
        for (int i = 0; i < 2; i++)
            #pragma unroll
            for (int hh = 0; hh < 2; hh++)
                psm[(wm + i * 16 + g + hh * 8) * 2 + (wn >> 6)] = rsum[i][hh];
    }
    __syncthreads();
    if (tid < 128)
        rs[((size_t)bh * S_ + qt * 128 + tid) * NKT_ + kt] = psm[tid * 2] + psm[tid * 2 + 1];
}

// ---------------- inv[row] = 1 / sum of valid partials ----------------
__global__ void rowsum_inv(const float* __restrict__ rs, float* __restrict__ inv) {
    int row = blockIdx.x * 256 + threadIdx.x;
    int qt = (row & (S_ - 1)) >> 7;
    float s = 0.f;
    for (int kt = 0; kt <= qt; kt++) s += rs[(size_t)row * NKT_ + kt];
    inv[row] = 1.0f / s;
}

// ---------------- zero strict-upper attn tiles ----------------
__global__ void zero_upper(float* __restrict__ attnP) {
    const int kt = blockIdx.x, qt = blockIdx.y, bh = blockIdx.z;
    if (kt <= qt) return;
    const int tid = threadIdx.x;
    float4 z = make_float4(0.f, 0.f, 0.f, 0.f);
    #pragma unroll
    for (int e = 0; e < 16; e++) {
        int u = tid + e * 256;          // 0..4095
        int r = u >> 5, c4 = u & 31;
        float4* p = (float4*)(attnP + ((size_t)bh * S_ + qt * 128 + r) * S_ + kt * 128);
        p[c4] = z;
    }
}

// =====================================================================
// ctx = (P' @ V) * inv; also writes normalized attn in-place.
// A (P') loaded via registers (write-back path), V via 3-stage cp.async.
// Block 128x64, warp tile 32x32. grid: (qt, BH)
// =====================================================================
__global__ __launch_bounds__(256, 2)
void attn_pv_norm(float* __restrict__ attnP, const float* __restrict__ V,
                  const float* __restrict__ inv, float* __restrict__ Ctx) {
    const int qt = blockIdx.x, bh = blockIdx.y;
    const int b = bh >> 4, h = bh & 15;

    __shared__ unsigned As[2][128][20];
    __shared__ unsigned Bs[3][16][72];

    const int tid = threadIdx.x;
    const int warp = tid >> 5, lane = tid & 31;
    const int g = lane >> 2, tg = lane & 3;
    const int wm = (warp >> 1) * 32, wn = (warp & 1) * 32;

    float* Ab = attnP + ((size_t)bh * S_ + qt * 128) * S_;
    const float* Vb = V + (size_t)b * S_ * D_ + h * DEPTH_;
    const float* invb = inv + (size_t)bh * S_ + qt * 128;

    const int rA = tid >> 2, kqA = (tid & 3) * 4;
    const int kB = tid >> 4, nqB = (tid & 15) * 4;

    const float iv0 = invb[rA], iv1 = invb[rA + 64];

    float c[2][4][4] = {};
    const int T = (qt + 1) * 8;

    // prologue: A regs for t=0; V stages 0,1
    float4 areg0 = *(const float4*)&Ab[(size_t)rA * S_ + kqA];
    float4 areg1 = *(const float4*)&Ab[(size_t)(rA + 64) * S_ + kqA];
    cp16(&Bs[0][kB][nqB], &Vb[(size_t)kB * D_ + nqB]);
    CP_COMMIT();
    cp16(&Bs[1][kB][nqB], &Vb[(size_t)(16 + kB) * D_ + nqB]);
    CP_COMMIT();

    for (int t = 0; t < T; t++) {
        if (t + 1 < T) CP_WAIT1(); else CP_WAIT0();
        __syncthreads();
        if (t + 2 < T) {
            cp16(&Bs[(t + 2) % 3][kB][nqB], &Vb[(size_t)((t + 2) * 16 + kB) * D_ + nqB]);
            CP_COMMIT();
        }
        float4 cur0 = areg0, cur1 = areg1;
        if (t + 1 < T) {
            areg0 = *(const float4*)&Ab[(size_t)rA * S_ + (t + 1) * 16 + kqA];
            areg1 = *(const float4*)&Ab[(size_t)(rA + 64) * S_ + (t + 1) * 16 + kqA];
        }
        // normalized write-back (in place)
        *(float4*)&Ab[(size_t)rA * S_ + t * 16 + kqA] =
            make_float4(cur0.x * iv0, cur0.y * iv0, cur0.z * iv0, cur0.w * iv0);
        *(float4*)&Ab[(size_t)(rA + 64) * S_ + t * 16 + kqA] =
            make_float4(cur1.x * iv1, cur1.y * iv1, cur1.z * iv1, cur1.w * iv1);
        // unnormalized tf32 to smem for MMA
        uint4 u0 = make_uint4(f2tf(cur0.x), f2tf(cur0.y), f2tf(cur0.z), f2tf(cur0.w));
        uint4 u1 = make_uint4(f2tf(cur1.x), f2tf(cur1.y), f2tf(cur1.z), f2tf(cur1.w));
        *(uint4*)&As[t & 1][rA][kqA] = u0;
        *(uint4*)&As[t & 1][rA + 64][kqA] = u1;
        __syncthreads();

        const int st = t & 1, sv = t % 3;
        #pragma unroll
        for (int ks = 0; ks < 16; ks += 8) {
            unsigned a[2][4], bfr[4][2];
            #pragma unroll
            for (int i = 0; i < 2; i++) {
                int mB = wm + i * 16;
                a[i][0] = As[st][mB + g    ][ks + tg    ];
                a[i][1] = As[st][mB + g + 8][ks + tg    ];
                a[i][2] = As[st][mB + g    ][ks + tg + 4];
                a[i][3] = As[st][mB + g + 8][ks + tg + 4];
            }
            #pragma unroll
            for (int j = 0; j < 4; j++) {
                int nB = wn + j * 8;
                bfr[j][0] = Bs[sv][ks + tg    ][nB + g];
                bfr[j][1] = Bs[sv][ks + tg + 4][nB + g];
            }
            #pragma unroll
            for (int i = 0; i < 2; i++)
                #pragma unroll
                for (int j = 0; j < 4; j++)
                    mma_tf32(c[i][j], a[i][0], a[i][1], a[i][2], a[i][3], bfr[j][0], bfr[j][1]);
        }
    }

    // epilogue: scale by inv, round to tf32, store ctx
    float ivr[2][2];
    #pragma unroll
    for (int i = 0; i < 2; i++)
        #pragma unroll
        for (int hh = 0; hh < 2; hh++)
            ivr[i][hh] = invb[wm + i * 16 + g + hh * 8];

    #pragma unroll
    for (int i = 0; i < 2; i++)
        #pragma unroll
        for (int j = 0; j < 4; j++) {
            int col = wn + j * 8 + tg * 2;
            #pragma unroll
            for (int hh = 0; hh < 2; hh++) {
                int row = qt * 128 + wm + i * 16 + g + hh * 8;
                int t = b * S_ + row;
                *(float2*)&Ctx[(size_t)t * D_ + h * DEPTH_ + col] =
                    make_float2(roundtf(c[i][j][hh * 2 + 0] * ivr[i][hh]),
                                roundtf(c[i][j][hh * 2 + 1] * ivr[i][hh]));
            }
        }
}

// ---------------- fused residual + LayerNorm ----------------
template <int WRITE_ROUND>
__global__ void ln_residual(const float* __restrict__ a, const float* __restrict__ bb,
                            const float* __restrict__ g, const float* __restrict__ be,
                            float* __restrict__ out, float* __restrict__ outr) {
    const int t = blockIdx.x;
    const int tid = threadIdx.x;
    float4 va = ((const float4*)(a  + (size_t)t * D_))[tid];
    float4 vb = ((const float4*)(bb + (size_t)t * D_))[tid];
    float4 v = make_float4(va.x + vb.x, va.y + vb.y, va.z + vb.z, va.w + vb.w);

    __shared__ float sm[256];
    sm[tid] = v.x + v.y + v.z + v.w; __syncthreads();
    for (int st = 128; st > 0; st >>= 1) { if (tid < st) sm[tid] += sm[tid + st]; __syncthreads(); }
    const float mu = sm[0] * (1.0f / D_);
    __syncthreads();

    float dx = v.x - mu, dy = v.y - mu, dz = v.z - mu, dw = v.w - mu;
    sm[tid] = dx * dx + dy * dy + dz * dz + dw * dw; __syncthreads();
    for (int st = 128; st > 0; st >>= 1) { if (tid < st) sm[tid] += sm[tid + st]; __syncthreads(); }
    const float inv = rsqrtf(sm[0] * (1.0f / D_) + EPS_);

    float4 gg = ((const float4*)g)[tid];
    float4 bz = ((const float4*)be)[tid];
    float4 o = make_float4(dx * inv * gg.x + bz.x, dy * inv * gg.y + bz.y,
                           dz * inv * gg.z + bz.z, dw * inv * gg.w + bz.w);
    ((float4*)(out + (size_t)t * D_))[tid] = o;
    if (WRITE_ROUND) {
        float4 orr = make_float4(roundtf(o.x), roundtf(o.y), roundtf(o.z), roundtf(o.w));
        ((float4*)(outr + (size_t)t * D_))[tid] = orr;
    }
}

// ---------------- launch ----------------
extern "C" void kernel_launch(void* const* d_in, const int* in_sizes, int n_in,
                              void* d_out, int out_size) {
    const float* x  = (const float*)d_in[0];
    const float* Wq = (const float*)d_in[2];  const float* bq = (const float*)d_in[3];
    const float* Wk = (const float*)d_in[4];  const float* bk = (const float*)d_in[5];
    const float* Wv = (const float*)d_in[6];  const float* bv = (const float*)d_in[7];
    const float* Wo = (const float*)d_in[8];  const float* bo = (const float*)d_in[9];
    const float* W1 = (const float*)d_in[10]; const float* b1 = (const float*)d_in[11];
    const float* W2 = (const float*)d_in[12]; const float* b2 = (const float*)d_in[13];
    const float* ln1g = (const float*)d_in[14]; const float* ln1b = (const float*)d_in[15];
    const float* ln2g = (const float*)d_in[16]; const float* ln2b = (const float*)d_in[17];

    float* out  = (float*)d_out;
    float* attn = out + (size_t)NT_ * D_;

    float *q, *k, *v, *ctx, *ao, *x1, *x1r, *h1, *ff2, *xr, *wr, *rs, *inv;
    cudaGetSymbolAddress((void**)&q,   g_q);
    cudaGetSymbolAddress((void**)&k,   g_k);
    cudaGetSymbolAddress((void**)&v,   g_v);
    cudaGetSymbolAddress((void**)&ctx, g_ctx);
    cudaGetSymbolAddress((void**)&ao,  g_ao);
    cudaGetSymbolAddress((void**)&x1,  g_x1);
    cudaGetSymbolAddress((void**)&x1r, g_x1r);
    cudaGetSymbolAddress((void**)&h1,  g_h1);
    cudaGetSymbolAddress((void**)&ff2, g_ff2);
    cudaGetSymbolAddress((void**)&xr,  g_xr);
    cudaGetSymbolAddress((void**)&wr,  g_wr);
    cudaGetSymbolAddress((void**)&rs,  g_rs);
    cudaGetSymbolAddress((void**)&inv, g_inv);

    float* Wqr = wr;
    float* Wkr = wr + 1048576;
    float* Wvr = wr + 2097152;
    float* Wor = wr + 3145728;
    float* W1r = wr + 4194304;
    float* W2r = wr + 8388608;

    const int GEMM_SMEM = 3 * (ASZ_ + BSZ_) * 4;       // 56832
    const int SC_SMEM   = 2 * 128 * 68 * 4;            // 69632
    cudaFuncSetAttribute(gemm_tf32p<0,1>, cudaFuncAttributeMaxDynamicSharedMemorySize, GEMM_SMEM);
    cudaFuncSetAttribute(gemm_tf32p<0,0>, cudaFuncAttributeMaxDynamicSharedMemorySize, GEMM_SMEM);
    cudaFuncSetAttribute(gemm_tf32p<1,1>, cudaFuncAttributeMaxDynamicSharedMemorySize, GEMM_SMEM);
    cudaFuncSetAttribute(attn_scores_exp, cudaFuncAttributeMaxDynamicSharedMemorySize, SC_SMEM);

    dim3 blk(256);

    round_copy<<<1024, blk>>>(Wq, Wqr, 262144);
    round_copy<<<1024, blk>>>(Wk, Wkr, 262144);
    round_copy<<<1024, blk>>>(Wv, Wvr, 262144);
    round_copy<<<1024, blk>>>(Wo, Wor, 262144);
    round_copy<<<4096, blk>>>(W1, W1r, 1048576);
    round_copy<<<4096, blk>>>(W2, W2r, 1048576);
    round_copy<<<4096, blk>>>(x,  xr,  1048576);

    dim3 gProj(D_ / 128, NT_ / 128);
    gemm_tf32p<0,1><<<gProj, blk, GEMM_SMEM>>>(xr, Wqr, bq, q, NT_, D_, D_);
    gemm_tf32p<0,1><<<gProj, blk, GEMM_SMEM>>>(xr, Wkr, bk, k, NT_, D_, D_);
    gemm_tf32p<0,1><<<gProj, blk, GEMM_SMEM>>>(xr, Wvr, bv, v, NT_, D_, D_);

    dim3 gScore(NKT_, NKT_, B_ * H_);
    attn_scores_exp<<<gScore, blk, SC_SMEM>>>(q, k, attn, rs);
    rowsum_inv<<<NROWS_ / 256, blk>>>(rs, inv);
    zero_upper<<<gScore, blk>>>(attn);

    dim3 gPV(NKT_, B_ * H_);
    attn_pv_norm<<<gPV, blk>>>(attn, v, inv, ctx);

    gemm_tf32p<0,0><<<gProj, blk, GEMM_SMEM>>>(ctx, Wor, bo, ao, NT_, D_, D_);
    ln_residual<1><<<NT_, blk>>>(x, ao, ln1g, ln1b, x1, x1r);

    dim3 gFF1(DFF_ / 128, NT_ / 128);
    gemm_tf32p<1,1><<<gFF1, blk, GEMM_SMEM>>>(x1r, W1r, b1, h1, NT_, DFF_, D_);
    gemm_tf32p<0,0><<<gProj, blk, GEMM_SMEM>>>(h1, W2r, b2, ff2, NT_, D_, DFF_);
    ln_residual<0><<<NT_, blk>>>(x1, ff2, ln2g, ln2b, out, nullptr);
}

// round 5
// speedup vs baseline: 1.0498x; 1.0498x over previous
#include <cuda_runtime.h>
#include <math.h>

#define B_ 2
#define S_ 2048
#define D_ 1024
#define H_ 16
#define DEPTH_ 64
#define DFF_ 4096
#define NT_ (B_ * S_)
#define EPS_ 1e-5f
#define LDQKV_ 3072

// ---------------- scratch ----------------
__device__ float g_qkv[NT_ * LDQKV_];
__device__ float g_wcat[D_ * LDQKV_];
__device__ float g_bcat[LDQKV_];
__device__ float g_ctx[NT_ * D_];
__device__ float g_ao [NT_ * D_];
__device__ float g_x1 [NT_ * D_];
__device__ float g_x1r[NT_ * D_];
__device__ float g_h1 [NT_ * DFF_];
__device__ float g_ff2[NT_ * D_];
__device__ float g_xr [NT_ * D_];
__device__ float g_wr [9437184];   // Wo(1M) W1(4M) W2(4M) floats

// ---------------- helpers ----------------
__device__ __forceinline__ unsigned f2tf(float x) {
    unsigned r;
    asm("cvt.rna.tf32.f32 %0, %1;" : "=r"(r) : "f"(x));
    return r;
}
__device__ __forceinline__ float roundtf(float x) { return __uint_as_float(f2tf(x)); }

__device__ __forceinline__ void mma_tf32(float c[4],
                                         unsigned a0, unsigned a1, unsigned a2, unsigned a3,
                                         unsigned b0, unsigned b1) {
    asm volatile(
        "mma.sync.aligned.m16n8k8.row.col.f32.tf32.tf32.f32 "
        "{%0,%1,%2,%3},{%4,%5,%6,%7},{%8,%9},{%0,%1,%2,%3};\n"
        : "+f"(c[0]), "+f"(c[1]), "+f"(c[2]), "+f"(c[3])
        : "r"(a0), "r"(a1), "r"(a2), "r"(a3), "r"(b0), "r"(b1));
}

__device__ __forceinline__ void cp16(void* smem, const void* gmem) {
    unsigned sa = (unsigned)__cvta_generic_to_shared(smem);
    asm volatile("cp.async.cg.shared.global [%0], [%1], 16;\n" :: "r"(sa), "l"(gmem));
}
#define CP_COMMIT() asm volatile("cp.async.commit_group;\n" ::)
#define CP_WAIT1()  asm volatile("cp.async.wait_group 1;\n" ::)
#define CP_WAIT0()  asm volatile("cp.async.wait_group 0;\n" ::)

// ---------------- rna rounding pre-passes ----------------
__global__ void round_copy(const float* __restrict__ src, float* __restrict__ dst, int n4) {
    int i = blockIdx.x * 256 + threadIdx.x;
    if (i < n4) {
        float4 t = ((const float4*)src)[i];
        t.x = roundtf(t.x); t.y = roundtf(t.y); t.z = roundtf(t.z); t.w = roundtf(t.w);
        ((float4*)dst)[i] = t;
    }
}
// copy [1024 x 1024] fp32 into dst rows of pitch 3072 at column offset
__global__ void round_copy_str(const float* __restrict__ src, float* __restrict__ dst, int coloff) {
    int i = blockIdx.x * 256 + threadIdx.x;       // one float4 each, 262144 total
    int row = i >> 8, c4 = i & 255;
    float4 t = ((const float4*)src)[i];
    t.x = roundtf(t.x); t.y = roundtf(t.y); t.z = roundtf(t.z); t.w = roundtf(t.w);
    ((float4*)(dst + (size_t)row * LDQKV_ + coloff))[c4] = t;
}

// =====================================================================
// Dense GEMM: block 256x128, ktile 16, 8 warps (4m x 2n), warp 64x64.
// 3-stage cp.async, single sync per k-iter.
// Dyn smem: 3*(256*20 + 16*136)*4 = 87552 B.
// =====================================================================
#define ASZ_ 5120
#define BSZ_ 2176
template <int GELU, int ROUND>
__global__ __launch_bounds__(256)
void gemm256(const float* __restrict__ A, const float* __restrict__ Bm,
             const float* __restrict__ bias, float* __restrict__ C,
             int M, int N, int K) {
    extern __shared__ unsigned dsm[];
    unsigned* Asp = dsm;              // [3][256][20]
    unsigned* Bsp = dsm + 3 * ASZ_;   // [3][16][136]

    const int tid = threadIdx.x;
    const int warp = tid >> 5, lane = tid & 31;
    const int g = lane >> 2, tg = lane & 3;
    const int m0 = blockIdx.y * 256, n0 = blockIdx.x * 128;
    const int wm = (warp >> 1) * 64, wn = (warp & 1) * 64;

    const int rA = tid >> 2,  kqA = (tid & 3) * 4;   // rows rA + i*64, i 0..3
    const int kB = tid >> 5,  nqB = (tid & 31) * 4;  // rows kB + i*8,  i 0..1

    float c[4][8][4] = {};
    const int T = K >> 4;

    #pragma unroll
    for (int s = 0; s < 2; s++) {
        const int k0 = s << 4;
        #pragma unroll
        for (int i = 0; i < 4; i++)
            cp16(&Asp[s * ASZ_ + (rA + i * 64) * 20 + kqA],
                 &A[(size_t)(m0 + rA + i * 64) * K + k0 + kqA]);
        #pragma unroll
        for (int i = 0; i < 2; i++)
            cp16(&Bsp[s * BSZ_ + (kB + i * 8) * 136 + nqB],
                 &Bm[(size_t)(k0 + kB + i * 8) * N + n0 + nqB]);
        CP_COMMIT();
    }

    for (int t = 0; t < T; t++) {
        if (t + 1 < T) CP_WAIT1(); else CP_WAIT0();
        __syncthreads();
        if (t + 2 < T) {
            const int s = (t + 2) % 3, k0 = (t + 2) << 4;
            #pragma unroll
            for (int i = 0; i < 4; i++)
                cp16(&Asp[s * ASZ_ + (rA + i * 64) * 20 + kqA],
                     &A[(size_t)(m0 + rA + i * 64) * K + k0 + kqA]);
            #pragma unroll
            for (int i = 0; i < 2; i++)
                cp16(&Bsp[s * BSZ_ + (kB + i * 8) * 136 + nqB],
                     &Bm[(size_t)(k0 + kB + i * 8) * N + n0 + nqB]);
            CP_COMMIT();
        }
        const unsigned* As = Asp + (t % 3) * ASZ_;
        const unsigned* Bs = Bsp + (t % 3) * BSZ_;
        #pragma unroll
        for (int ks = 0; ks < 16; ks += 8) {
            unsigned a[4][4], b[8][2];
            #pragma unroll
            for (int i = 0; i < 4; i++) {
                int mB = wm + i * 16;
                a[i][0] = As[(mB + g    ) * 20 + ks + tg    ];
                a[i][1] = As[(mB + g + 8) * 20 + ks + tg    ];
                a[i][2] = As[(mB + g    ) * 20 + ks + tg + 4];
                a[i][3] = As[(mB + g + 8) * 20 + ks + tg + 4];
            }
            #pragma unroll
            for (int j = 0; j < 8; j++) {
                int nB = wn + j * 8;
                b[j][0] = Bs[(ks + tg    ) * 136 + nB + g];
                b[j][1] = Bs[(ks + tg + 4) * 136 + nB + g];
            }
            #pragma unroll
            for (int i = 0; i < 4; i++)
                #pragma unroll
                for (int j = 0; j < 8; j++)
                    mma_tf32(c[i][j], a[i][0], a[i][1], a[i][2], a[i][3], b[j][0], b[j][1]);
        }
    }

    #pragma unroll
    for (int i = 0; i < 4; i++) {
        #pragma unroll
        for (int j = 0; j < 8; j++) {
            int col = n0 + wn + j * 8 + tg * 2;
            float b0v = bias[col], b1v = bias[col + 1];
            #pragma unroll
            for (int h = 0; h < 2; h++) {
                int row = m0 + wm + i * 16 + g + h * 8;
                float v0 = c[i][j][h * 2 + 0] + b0v;
                float v1 = c[i][j][h * 2 + 1] + b1v;
                if (GELU) {
                    v0 = 0.5f * v0 * (1.0f + erff(v0 * 0.70710678118654752f));
                    v1 = 0.5f * v1 * (1.0f + erff(v1 * 0.70710678118654752f));
                }
                if (ROUND) { v0 = roundtf(v0); v1 = roundtf(v1); }
                *(float2*)&C[(size_t)row * N + col] = make_float2(v0, v1);
            }
        }
    }
}

// =====================================================================
// Attention scores, 2-stage pipeline over DEPTH=64. Q,K pre-rounded.
// Q/K live in fused qkv buffer, row pitch LDQKV_.
// =====================================================================
__global__ __launch_bounds__(256, 2)
void attn_scores_tc(const float* __restrict__ QKV, float* __restrict__ attnP) {
    const int kt = blockIdx.x, qt = blockIdx.y, bh = blockIdx.z;
    if (kt > qt) return;
    const int b = bh >> 4, h = bh & 15;

    __shared__ unsigned As[2][128][20];
    __shared__ unsigned Bt[2][128][20];

    const int tid = threadIdx.x;
    const int warp = tid >> 5, lane = tid & 31;
    const int g = lane >> 2, tg = lane & 3;
    const int wm = (warp >> 1) * 32, wn = (warp & 1) * 64;

    const float* qb = QKV + (size_t)(b * S_ + qt * 128) * LDQKV_ + h * DEPTH_;
    const float* kb = QKV + (size_t)(b * S_ + kt * 128) * LDQKV_ + 1024 + h * DEPTH_;

    const int r = tid >> 2, kq = (tid & 3) * 4;

    float c[2][8][4] = {};

    #pragma unroll
    for (int i = 0; i < 2; i++) {
        cp16(&As[0][r + i * 64][kq], &qb[(size_t)(r + i * 64) * LDQKV_ + kq]);
        cp16(&Bt[0][r + i * 64][kq], &kb[(size_t)(r + i * 64) * LDQKV_ + kq]);
    }
    CP_COMMIT();

    #pragma unroll
    for (int t = 0; t < 4; t++) {
        if (t < 3) {
            const int k0 = (t + 1) << 4, st = (t + 1) & 1;
            #pragma unroll
            for (int i = 0; i < 2; i++) {
                cp16(&As[st][r + i * 64][kq], &qb[(size_t)(r + i * 64) * LDQKV_ + k0 + kq]);
                cp16(&Bt[st][r + i * 64][kq], &kb[(size_t)(r + i * 64) * LDQKV_ + k0 + kq]);
            }
            CP_COMMIT();
            CP_WAIT1();
        } else {
            CP_WAIT0();
        }
        __syncthreads();
        const int st = t & 1;
        #pragma unroll
        for (int ks = 0; ks < 16; ks += 8) {
            unsigned a[2][4], bfr[8][2];
            #pragma unroll
            for (int i = 0; i < 2; i++) {
                int mB = wm + i * 16;
                a[i][0] = As[st][mB + g    ][ks + tg    ];
                a[i][1] = As[st][mB + g + 8][ks + tg    ];
                a[i][2] = As[st][mB + g    ][ks + tg + 4];
                a[i][3] = As[st][mB + g + 8][ks + tg + 4];
            }
            #pragma unroll
            for (int j = 0; j < 8; j++) {
                int nB = wn + j * 8;
                bfr[j][0] = Bt[st][nB + g][ks + tg    ];
                bfr[j][1] = Bt[st][nB + g][ks + tg + 4];
            }
            #pragma unroll
            for (int i = 0; i < 2; i++)
                #pragma unroll
                for (int j = 0; j < 8; j++)
                    mma_tf32(c[i][j], a[i][0], a[i][1], a[i][2], a[i][3], bfr[j][0], bfr[j][1]);
        }
        __syncthreads();
    }

    float* ob = attnP + ((size_t)bh * S_ + qt * 128) * S_ + kt * 128;
    #pragma unroll
    for (int i = 0; i < 2; i++)
        #pragma unroll
        for (int j = 0; j < 8; j++) {
            int col = wn + j * 8 + tg * 2;
            #pragma unroll
            for (int h = 0; h < 2; h++) {
                int row = wm + i * 16 + g + h * 8;
                *(float2*)&ob[(size_t)row * S_ + col] =
                    make_float2(c[i][j][h * 2 + 0] * 0.03125f, c[i][j][h * 2 + 1] * 0.03125f);
            }
        }
}

// =====================================================================
// Causal softmax, no max-subtraction (scores are O(1)); in-place.
// Reads valid prefix only, writes full row (zero tail).
// =====================================================================
__global__ void softmax_rows(float* __restrict__ attnP) {
    const int row = blockIdx.x;
    const int q = row & (S_ - 1);
    float4* p = (float4*)(attnP + (size_t)row * S_);
    const int tid = threadIdx.x;

    float4 v[2];
    float sum = 0.f;
    #pragma unroll
    for (int i = 0; i < 2; i++) {
        int b4 = tid + i * 256;
        int e0 = b4 * 4;
        if (e0 <= q) {
            float4 t = p[b4];
            t.x = (e0 + 0 <= q) ? __expf(t.x) : 0.f;
            t.y = (e0 + 1 <= q) ? __expf(t.y) : 0.f;
            t.z = (e0 + 2 <= q) ? __expf(t.z) : 0.f;
            t.w = (e0 + 3 <= q) ? __expf(t.w) : 0.f;
            v[i] = t;
            sum += t.x + t.y + t.z + t.w;
        } else {
            v[i] = make_float4(0.f, 0.f, 0.f, 0.f);
        }
    }
    __shared__ float sm[256];
    sm[tid] = sum; __syncthreads();
    for (int s = 128; s > 0; s >>= 1) { if (tid < s) sm[tid] += sm[tid + s]; __syncthreads(); }
    const float inv = 1.0f / sm[0];

    #pragma unroll
    for (int i = 0; i < 2; i++) {
        int b4 = tid + i * 256;
        v[i].x *= inv; v[i].y *= inv; v[i].z *= inv; v[i].w *= inv;
        p[b4] = v[i];
    }
}

// =====================================================================
// ctx = attn @ V, 2-stage pipeline. V in fused qkv buffer (offset 2048).
// Block 128x64, warp 32x32. grid: (qt, BH)
// =====================================================================
__global__ __launch_bounds__(256, 2)
void attn_pv_tc(const float* __restrict__ P, const float* __restrict__ QKV,
                float* __restrict__ Ctx) {
    const int qt = blockIdx.x, bh = blockIdx.y;
    const int b = bh >> 4, h = bh & 15;

    __shared__ unsigned As[2][128][20];
    __shared__ unsigned Bs[2][16][72];

    const int tid = threadIdx.x;
    const int warp = tid >> 5, lane = tid & 31;
    const int g = lane >> 2, tg = lane & 3;
    const int wm = (warp >> 1) * 32, wn = (warp & 1) * 32;

    const float* Ab = P + ((size_t)bh * S_ + qt * 128) * S_;
    const float* Vb = QKV + (size_t)(b * S_) * LDQKV_ + 2048 + h * DEPTH_;

    const int rA = tid >> 2, kqA = (tid & 3) * 4;
    const int kB = tid >> 4, nqB = (tid & 15) * 4;

    float c[2][4][4] = {};
    const int T = (qt + 1) * 8;

    #pragma unroll
    for (int i = 0; i < 2; i++)
        cp16(&As[0][rA + i * 64][kqA], &Ab[(size_t)(rA + i * 64) * S_ + kqA]);
    cp16(&Bs[0][kB][nqB], &Vb[(size_t)kB * LDQKV_ + nqB]);
    CP_COMMIT();

    for (int t = 0; t < T; t++) {
        if (t + 1 < T) {
            const int k0 = (t + 1) << 4, st = (t + 1) & 1;
            #pragma unroll
            for (int i = 0; i < 2; i++)
                cp16(&As[st][rA + i * 64][kqA], &Ab[(size_t)(rA + i * 64) * S_ + k0 + kqA]);
            cp16(&Bs[st][kB][nqB], &Vb[(size_t)(k0 + kB) * LDQKV_ + nqB]);
            CP_COMMIT();
            CP_WAIT1();
        } else {
            CP_WAIT0();
        }
        __syncthreads();
        const int st = t & 1;
        #pragma unroll
        for (int ks = 0; ks < 16; ks += 8) {
            unsigned a[2][4], bfr[4][2];
            #pragma unroll
            for (int i = 0; i < 2; i++) {
                int mB = wm + i * 16;
                a[i][0] = As[st][mB + g    ][ks + tg    ];
                a[i][1] = As[st][mB + g + 8][ks + tg    ];
                a[i][2] = As[st][mB + g    ][ks + tg + 4];
                a[i][3] = As[st][mB + g + 8][ks + tg + 4];
            }
            #pragma unroll
            for (int j = 0; j < 4; j++) {
                int nB = wn + j * 8;
                bfr[j][0] = Bs[st][ks + tg    ][nB + g];
                bfr[j][1] = Bs[st][ks + tg + 4][nB + g];
            }
            #pragma unroll
            for (int i = 0; i < 2; i++)
                #pragma unroll
                for (int j = 0; j < 4; j++)
                    mma_tf32(c[i][j], a[i][0], a[i][1], a[i][2], a[i][3], bfr[j][0], bfr[j][1]);
        }
        __syncthreads();
    }

    #pragma unroll
    for (int i = 0; i < 2; i++)
        #pragma unroll
        for (int j = 0; j < 4; j++) {
            int col = wn + j * 8 + tg * 2;
            #pragma unroll
            for (int hh = 0; hh < 2; hh++) {
                int row = qt * 128 + wm + i * 16 + g + hh * 8;
                int t = b * S_ + row;
                *(float2*)&Ctx[(size_t)t * D_ + h * DEPTH_ + col] =
                    make_float2(roundtf(c[i][j][hh * 2 + 0]), roundtf(c[i][j][hh * 2 + 1]));
            }
        }
}

// ---------------- fused residual + LayerNorm ----------------
template <int WRITE_ROUND>
__global__ void ln_residual(const float* __restrict__ a, const float* __restrict__ bb,
                            const float* __restrict__ g, const float* __restrict__ be,
                            float* __restrict__ out, float* __restrict__ outr) {
    const int t = blockIdx.x;
    const int tid = threadIdx.x;
    float4 va = ((const float4*)(a  + (size_t)t * D_))[tid];
    float4 vb = ((const float4*)(bb + (size_t)t * D_))[tid];
    float4 v = make_float4(va.x + vb.x, va.y + vb.y, va.z + vb.z, va.w + vb.w);

    __shared__ float sm[256];
    sm[tid] = v.x + v.y + v.z + v.w; __syncthreads();
    for (int st = 128; st > 0; st >>= 1) { if (tid < st) sm[tid] += sm[tid + st]; __syncthreads(); }
    const float mu = sm[0] * (1.0f / D_);
    __syncthreads();

    float dx = v.x - mu, dy = v.y - mu, dz = v.z - mu, dw = v.w - mu;
    sm[tid] = dx * dx + dy * dy + dz * dz + dw * dw; __syncthreads();
    for (int st = 128; st > 0; st >>= 1) { if (tid < st) sm[tid] += sm[tid + st]; __syncthreads(); }
    const float inv = rsqrtf(sm[0] * (1.0f / D_) + EPS_);

    float4 gg = ((const float4*)g)[tid];
    float4 bz = ((const float4*)be)[tid];
    float4 o = make_float4(dx * inv * gg.x + bz.x, dy * inv * gg.y + bz.y,
                           dz * inv * gg.z + bz.z, dw * inv * gg.w + bz.w);
    ((float4*)(out + (size_t)t * D_))[tid] = o;
    if (WRITE_ROUND) {
        float4 orr = make_float4(roundtf(o.x), roundtf(o.y), roundtf(o.z), roundtf(o.w));
        ((float4*)(outr + (size_t)t * D_))[tid] = orr;
    }
}

// ---------------- launch ----------------
extern "C" void kernel_launch(void* const* d_in, const int* in_sizes, int n_in,
                              void* d_out, int out_size) {
    const float* x  = (const float*)d_in[0];
    const float* Wq = (const float*)d_in[2];  const float* bq = (const float*)d_in[3];
    const float* Wk = (const float*)d_in[4];  const float* bk = (const float*)d_in[5];
    const float* Wv = (const float*)d_in[6];  const float* bv = (const float*)d_in[7];
    const float* Wo = (const float*)d_in[8];  const float* bo = (const float*)d_in[9];
    const float* W1 = (const float*)d_in[10]; const float* b1 = (const float*)d_in[11];
    const float* W2 = (const float*)d_in[12]; const float* b2 = (const float*)d_in[13];
    const float* ln1g = (const float*)d_in[14]; const float* ln1b = (const float*)d_in[15];
    const float* ln2g = (const float*)d_in[16]; const float* ln2b = (const float*)d_in[17];

    float* out  = (float*)d_out;
    float* attn = out + (size_t)NT_ * D_;

    float *qkv, *wcat, *bcat, *ctx, *ao, *x1, *x1r, *h1, *ff2, *xr, *wr;
    cudaGetSymbolAddress((void**)&qkv,  g_qkv);
    cudaGetSymbolAddress((void**)&wcat, g_wcat);
    cudaGetSymbolAddress((void**)&bcat, g_bcat);
    cudaGetSymbolAddress((void**)&ctx,  g_ctx);
    cudaGetSymbolAddress((void**)&ao,   g_ao);
    cudaGetSymbolAddress((void**)&x1,   g_x1);
    cudaGetSymbolAddress((void**)&x1r,  g_x1r);
    cudaGetSymbolAddress((void**)&h1,   g_h1);
    cudaGetSymbolAddress((void**)&ff2,  g_ff2);
    cudaGetSymbolAddress((void**)&xr,   g_xr);
    cudaGetSymbolAddress((void**)&wr,   g_wr);

    float* Wor = wr;
    float* W1r = wr + 1048576;
    float* W2r = wr + 5242880;

    const int GEMM_SMEM = 3 * (ASZ_ + BSZ_) * 4;       // 87552
    cudaFuncSetAttribute(gemm256<0,1>, cudaFuncAttributeMaxDynamicSharedMemorySize, GEMM_SMEM);
    cudaFuncSetAttribute(gemm256<0,0>, cudaFuncAttributeMaxDynamicSharedMemorySize, GEMM_SMEM);
    cudaFuncSetAttribute(gemm256<1,1>, cudaFuncAttributeMaxDynamicSharedMemorySize, GEMM_SMEM);

    dim3 blk(256);

    // rounded weight prep: QKV concat + Wo/W1/W2 + x
    round_copy_str<<<1024, blk>>>(Wq, wcat, 0);
    round_copy_str<<<1024, blk>>>(Wk, wcat, 1024);
    round_copy_str<<<1024, blk>>>(Wv, wcat, 2048);
    cudaMemcpyAsync(bcat,        bq, D_ * 4, cudaMemcpyDeviceToDevice);
    cudaMemcpyAsync(bcat + 1024, bk, D_ * 4, cudaMemcpyDeviceToDevice);
    cudaMemcpyAsync(bcat + 2048, bv, D_ * 4, cudaMemcpyDeviceToDevice);
    round_copy<<<1024, blk>>>(Wo, Wor, 262144);
    round_copy<<<4096, blk>>>(W1, W1r, 1048576);
    round_copy<<<4096, blk>>>(W2, W2r, 1048576);
    round_copy<<<4096, blk>>>(x,  xr,  1048576);

    // fused QKV projection: [4096,1024] @ [1024,3072]
    dim3 gQKV(LDQKV_ / 128, NT_ / 256);         // (24, 16)
    gemm256<0,1><<<gQKV, blk, GEMM_SMEM>>>(xr, wcat, bcat, qkv, NT_, LDQKV_, D_);

    dim3 gScore(S_ / 128, S_ / 128, B_ * H_);   // (16, 16, 32)
    attn_scores_tc<<<gScore, blk>>>(qkv, attn);

    softmax_rows<<<B_ * H_ * S_, blk>>>(attn);

    dim3 gPV(S_ / 128, B_ * H_);                // (16, 32)
    attn_pv_tc<<<gPV, blk>>>(attn, qkv, ctx);

    dim3 gO(D_ / 128, NT_ / 256);               // (8, 16)
    gemm256<0,0><<<gO, blk, GEMM_SMEM>>>(ctx, Wor, bo, ao, NT_, D_, D_);
    ln_residual<1><<<NT_, blk>>>(x, ao, ln1g, ln1b, x1, x1r);

    dim3 gFF1(DFF_ / 128, NT_ / 256);           // (32, 16)
    gemm256<1,1><<<gFF1, blk, GEMM_SMEM>>>(x1r, W1r, b1, h1, NT_, DFF_, D_);
    gemm256<0,0><<<gO, blk, GEMM_SMEM>>>(h1, W2r, b2, ff2, NT_, D_, DFF_);
    ln_residual<0><<<NT_, blk>>>(x1, ff2, ln2g, ln2b, out, nullptr);
}

// round 7
// speedup vs baseline: 1.1907x; 1.1341x over previous
#include <cuda_runtime.h>
#include <math.h>

#define B_ 2
#define S_ 2048
#define D_ 1024
#define H_ 16
#define DEPTH_ 64
#define DFF_ 4096
#define NT_ (B_ * S_)
#define EPS_ 1e-5f
#define LDQKV_ 3072
#define NROWS_ (B_ * H_ * S_)
#define NKT_ 16

// ---------------- scratch ----------------
__device__ float g_qkv[NT_ * LDQKV_];
__device__ float g_wcat[D_ * LDQKV_];
__device__ float g_bcat[LDQKV_];
__device__ float g_ctx[NT_ * D_];
__device__ float g_ao [NT_ * D_];
__device__ float g_x1 [NT_ * D_];
__device__ float g_x1r[NT_ * D_];
__device__ float g_h1 [NT_ * DFF_];
__device__ float g_ff2[NT_ * D_];
__device__ float g_xr [NT_ * D_];
__device__ float g_wr [9437184];        // Wo(1M) W1(4M) W2(4M)
__device__ float g_rs [NROWS_ * NKT_];  // partial row sums
__device__ float g_inv[NROWS_];         // 1/rowsum

// ---------------- helpers ----------------
__device__ __forceinline__ unsigned f2tf(float x) {
    unsigned r;
    asm("cvt.rna.tf32.f32 %0, %1;" : "=r"(r) : "f"(x));
    return r;
}
__device__ __forceinline__ float roundtf(float x) { return __uint_as_float(f2tf(x)); }

__device__ __forceinline__ void mma_tf32(float c[4],
                                         unsigned a0, unsigned a1, unsigned a2, unsigned a3,
                                         unsigned b0, unsigned b1) {
    asm volatile(
        "mma.sync.aligned.m16n8k8.row.col.f32.tf32.tf32.f32 "
        "{%0,%1,%2,%3},{%4,%5,%6,%7},{%8,%9},{%0,%1,%2,%3};\n"
        : "+f"(c[0]), "+f"(c[1]), "+f"(c[2]), "+f"(c[3])
        : "r"(a0), "r"(a1), "r"(a2), "r"(a3), "r"(b0), "r"(b1));
}

__device__ __forceinline__ void cp16(void* smem, const void* gmem) {
    unsigned sa = (unsigned)__cvta_generic_to_shared(smem);
    asm volatile("cp.async.cg.shared.global [%0], [%1], 16;\n" :: "r"(sa), "l"(gmem));
}
#define CP_COMMIT() asm volatile("cp.async.commit_group;\n" ::)
#define CP_WAIT1()  asm volatile("cp.async.wait_group 1;\n" ::)
#define CP_WAIT0()  asm volatile("cp.async.wait_group 0;\n" ::)

// ---------------- rna rounding pre-passes ----------------
__global__ void round_copy(const float* __restrict__ src, float* __restrict__ dst, int n4) {
    int i = blockIdx.x * 256 + threadIdx.x;
    if (i < n4) {
        float4 t = ((const float4*)src)[i];
        t.x = roundtf(t.x); t.y = roundtf(t.y); t.z = roundtf(t.z); t.w = roundtf(t.w);
        ((float4*)dst)[i] = t;
    }
}
__global__ void round_copy_str(const float* __restrict__ src, float* __restrict__ dst, int coloff) {
    int i = blockIdx.x * 256 + threadIdx.x;
    int row = i >> 8, c4 = i & 255;
    float4 t = ((const float4*)src)[i];
    t.x = roundtf(t.x); t.y = roundtf(t.y); t.z = roundtf(t.z); t.w = roundtf(t.w);
    ((float4*)(dst + (size_t)row * LDQKV_ + coloff))[c4] = t;
}

// =====================================================================
// Dense GEMM, 3-stage cp.async, one sync per k-iter. 128x128, 8 warps.
// =====================================================================
#define ASZ_ 2560
#define BSZ_ 2176
template <int GELU, int ROUND>
__global__ __launch_bounds__(256, 2)
void gemm_tf32p(const float* __restrict__ A, const float* __restrict__ Bm,
                const float* __restrict__ bias, float* __restrict__ C,
                int M, int N, int K) {
    extern __shared__ unsigned dsm[];
    unsigned* Asp = dsm;
    unsigned* Bsp = dsm + 3 * ASZ_;

    const int tid = threadIdx.x;
    const int warp = tid >> 5, lane = tid & 31;
    const int g = lane >> 2, tg = lane & 3;
    const int m0 = blockIdx.y * 128, n0 = blockIdx.x * 128;
    const int wm = (warp >> 1) * 32, wn = (warp & 1) * 64;

    const int rA = tid >> 2,  kqA = (tid & 3) * 4;
    const int kB = tid >> 5,  nqB = (tid & 31) * 4;

    float c[2][8][4] = {};
    const int T = K >> 4;

    #pragma unroll
    for (int s = 0; s < 2; s++) {
        const int k0 = s << 4;
        #pragma unroll
        for (int i = 0; i < 2; i++)
            cp16(&Asp[s * ASZ_ + (rA + i * 64) * 20 + kqA],
                 &A[(size_t)(m0 + rA + i * 64) * K + k0 + kqA]);
        #pragma unroll
        for (int i = 0; i < 2; i++)
            cp16(&Bsp[s * BSZ_ + (kB + i * 8) * 136 + nqB],
                 &Bm[(size_t)(k0 + kB + i * 8) * N + n0 + nqB]);
        CP_COMMIT();
    }

    for (int t = 0; t < T; t++) {
        if (t + 1 < T) CP_WAIT1(); else CP_WAIT0();
        __syncthreads();
        if (t + 2 < T) {
            const int s = (t + 2) % 3, k0 = (t + 2) << 4;
            #pragma unroll
            for (int i = 0; i < 2; i++)
                cp16(&Asp[s * ASZ_ + (rA + i * 64) * 20 + kqA],
                     &A[(size_t)(m0 + rA + i * 64) * K + k0 + kqA]);
            #pragma unroll
            for (int i = 0; i < 2; i++)
                cp16(&Bsp[s * BSZ_ + (kB + i * 8) * 136 + nqB],
                     &Bm[(size_t)(k0 + kB + i * 8) * N + n0 + nqB]);
            CP_COMMIT();
        }
        const unsigned* As = Asp + (t % 3) * ASZ_;
        const unsigned* Bs = Bsp + (t % 3) * BSZ_;
        #pragma unroll
        for (int ks = 0; ks < 16; ks += 8) {
            unsigned a[2][4], b[8][2];
            #pragma unroll
            for (int i = 0; i < 2; i++) {
                int mB = wm + i * 16;
                a[i][0] = As[(mB + g    ) * 20 + ks + tg    ];
                a[i][1] = As[(mB + g + 8) * 20 + ks + tg    ];
                a[i][2] = As[(mB + g    ) * 20 + ks + tg + 4];
                a[i][3] = As[(mB + g + 8) * 20 + ks + tg + 4];
            }
            #pragma unroll
            for (int j = 0; j < 8; j++) {
                int nB = wn + j * 8;
                b[j][0] = Bs[(ks + tg    ) * 136 + nB + g];
                b[j][1] = Bs[(ks + tg + 4) * 136 + nB + g];
            }
            #pragma unroll
            for (int i = 0; i < 2; i++)
                #pragma unroll
                for (int j = 0; j < 8; j++)
                    mma_tf32(c[i][j], a[i][0], a[i][1], a[i][2], a[i][3], b[j][0], b[j][1]);
        }
    }

    #pragma unroll
    for (int i = 0; i < 2; i++) {
        #pragma unroll
        for (int j = 0; j < 8; j++) {
            int col = n0 + wn + j * 8 + tg * 2;
            float b0v = bias[col], b1v = bias[col + 1];
            #pragma unroll
            for (int h = 0; h < 2; h++) {
                int row = m0 + wm + i * 16 + g + h * 8;
                float v0 = c[i][j][h * 2 + 0] + b0v;
                float v1 = c[i][j][h * 2 + 1] + b1v;
                if (GELU) {
                    v0 = 0.5f * v0 * (1.0f + erff(v0 * 0.70710678118654752f));
                    v1 = 0.5f * v1 * (1.0f + erff(v1 * 0.70710678118654752f));
                }
                if (ROUND) { v0 = roundtf(v0); v1 = roundtf(v1); }
                *(float2*)&C[(size_t)row * N + col] = make_float2(v0, v1);
            }
        }
    }
}

// =====================================================================
// Scores + exp + partial row sums. Q/K from fused qkv buffer.
// Dyn smem 2*128*68*4 = 69632 B.
// =====================================================================
__global__ __launch_bounds__(256, 2)
void attn_scores_exp(const float* __restrict__ QKV, float* __restrict__ attnP,
                     float* __restrict__ rs) {
    const int kt = blockIdx.x, qt = blockIdx.y, bh = blockIdx.z;
    if (kt > qt) return;
    const int b = bh >> 4, h = bh & 15;

    extern __shared__ unsigned dsm[];
    unsigned* Qs = dsm;              // [128][68]
    unsigned* Ks = dsm + 128 * 68;

    const int tid = threadIdx.x;
    const int warp = tid >> 5, lane = tid & 31;
    const int g = lane >> 2, tg = lane & 3;
    const int wm = (warp >> 1) * 32, wn = (warp & 1) * 64;

    const float* qb = QKV + (size_t)(b * S_ + qt * 128) * LDQKV_ + h * DEPTH_;
    const float* kb = QKV + (size_t)(b * S_ + kt * 128) * LDQKV_ + 1024 + h * DEPTH_;

    #pragma unroll
    for (int e = 0; e < 8; e++) {
        int u = tid + e * 256;
        int r = u >> 4, cc = (u & 15) * 4;
        cp16(&Qs[r * 68 + cc], &qb[(size_t)r * LDQKV_ + cc]);
        cp16(&Ks[r * 68 + cc], &kb[(size_t)r * LDQKV_ + cc]);
    }
    CP_COMMIT();
    CP_WAIT0();
    __syncthreads();

    float c[2][8][4] = {};
    #pragma unroll
    for (int ks = 0; ks < 64; ks += 8) {
        unsigned a[2][4], bfr[8][2];
        #pragma unroll
        for (int i = 0; i < 2; i++) {
            int mB = wm + i * 16;
            a[i][0] = Qs[(mB + g    ) * 68 + ks + tg    ];
            a[i][1] = Qs[(mB + g + 8) * 68 + ks + tg    ];
            a[i][2] = Qs[(mB + g    ) * 68 + ks + tg + 4];
            a[i][3] = Qs[(mB + g + 8) * 68 + ks + tg + 4];
        }
        #pragma unroll
        for (int j = 0; j < 8; j++) {
            int nB = wn + j * 8;
            bfr[j][0] = Ks[(nB + g) * 68 + ks + tg    ];
            bfr[j][1] = Ks[(nB + g) * 68 + ks + tg + 4];
        }
        #pragma unroll
        for (int i = 0; i < 2; i++)
            #pragma unroll
            for (int j = 0; j < 8; j++)
                mma_tf32(c[i][j], a[i][0], a[i][1], a[i][2], a[i][3], bfr[j][0], bfr[j][1]);
    }

    const bool diag = (kt == qt);
    float rsum[2][2] = {};
    float* ob = attnP + ((size_t)bh * S_ + qt * 128) * S_ + kt * 128;
    #pragma unroll
    for (int i = 0; i < 2; i++)
        #pragma unroll
        for (int j = 0; j < 8; j++) {
            int col = wn + j * 8 + tg * 2;
            #pragma unroll
            for (int hh = 0; hh < 2; hh++) {
                int row = wm + i * 16 + g + hh * 8;
                float v0 = __expf(c[i][j][hh * 2 + 0] * 0.03125f);
                float v1 = __expf(c[i][j][hh * 2 + 1] * 0.03125f);
                if (diag) {
                    if (col     > row) v0 = 0.f;
                    if (col + 1 > row) v1 = 0.f;
                }
                rsum[i][hh] += v0 + v1;
                *(float2*)&ob[(size_t)row * S_ + col] = make_float2(v0, v1);
            }
        }

    #pragma unroll
    for (int i = 0; i < 2; i++)
        #pragma unroll
        for (int hh = 0; hh < 2; hh++) {
            rsum[i][hh] += __shfl_xor_sync(0xffffffff, rsum[i][hh], 1);
            rsum[i][hh] += __shfl_xor_sync(0xffffffff, rsum[i][hh], 2);
        }
    __syncthreads();
    float* psm = (float*)Qs;
    if (tg == 0) {
        #pragma unroll
        for (int i = 0; i < 2; i++)
            #pragma unroll
            for (int hh = 0; hh < 2; hh++)
                psm[(wm + i * 16 + g + hh * 8) * 2 + (wn >> 6)] = rsum[i][hh];
    }
    __syncthreads();
    if (tid < 128)
        rs[((size_t)bh * S_ + qt * 128 + tid) * NKT_ + kt] = psm[tid * 2] + psm[tid * 2 + 1];
}

// ---------------- inv[row] = 1 / sum of valid partials ----------------
__global__ void rowsum_inv(const float* __restrict__ rs, float* __restrict__ inv) {
    int row = blockIdx.x * 256 + threadIdx.x;
    int qt = (row & (S_ - 1)) >> 7;
    float s = 0.f;
    for (int kt = 0; kt <= qt; kt++) s += rs[(size_t)row * NKT_ + kt];
    inv[row] = 1.0f / s;
}

// ---------------- zero strict-upper attn tiles ----------------
__global__ void zero_upper(float* __restrict__ attnP) {
    const int kt = blockIdx.x, qt = blockIdx.y, bh = blockIdx.z;
    if (kt <= qt) return;
    const int tid = threadIdx.x;
    float4 z = make_float4(0.f, 0.f, 0.f, 0.f);
    #pragma unroll
    for (int e = 0; e < 16; e++) {
        int u = tid + e * 256;
        int r = u >> 5, c4 = u & 31;
        float4* p = (float4*)(attnP + ((size_t)bh * S_ + qt * 128 + r) * S_ + kt * 128);
        p[c4] = z;
    }
}

// =====================================================================
// ctx = (P' @ V) * inv; writes normalized attn back FROM SMEM in-loop.
// R3/R5 PV skeleton: 2-stage cp.async, one sync per iter.
// grid (qt, BH), block 128x64, warp 32x32.
// =====================================================================
__global__ __launch_bounds__(256, 2)
void attn_pv_norm(float* __restrict__ attnP, const float* __restrict__ QKV,
                  const float* __restrict__ inv, float* __restrict__ Ctx) {
    const int qt = blockIdx.x, bh = blockIdx.y;
    const int b = bh >> 4, h = bh & 15;

    __shared__ unsigned As[2][128][20];
    __shared__ unsigned Bs[2][16][72];

    const int tid = threadIdx.x;
    const int warp = tid >> 5, lane = tid & 31;
    const int g = lane >> 2, tg = lane & 3;
    const int wm = (warp >> 1) * 32, wn = (warp & 1) * 32;

    float* Ab = attnP + ((size_t)bh * S_ + qt * 128) * S_;
    const float* Vb = QKV + (size_t)(b * S_) * LDQKV_ + 2048 + h * DEPTH_;
    const float* invb = inv + (size_t)bh * S_ + qt * 128;

    const int rA = tid >> 2, kqA = (tid & 3) * 4;
    const int kB = tid >> 4, nqB = (tid & 15) * 4;

    const float iv0 = invb[rA], iv1 = invb[rA + 64];

    float c[2][4][4] = {};
    const int T = (qt + 1) * 8;

    #pragma unroll
    for (int i = 0; i < 2; i++)
        cp16(&As[0][rA + i * 64][kqA], &Ab[(size_t)(rA + i * 64) * S_ + kqA]);
    cp16(&Bs[0][kB][nqB], &Vb[(size_t)kB * LDQKV_ + nqB]);
    CP_COMMIT();

    for (int t = 0; t < T; t++) {
        if (t + 1 < T) {
            const int k0 = (t + 1) << 4, st = (t + 1) & 1;
            #pragma unroll
            for (int i = 0; i < 2; i++)
                cp16(&As[st][rA + i * 64][kqA], &Ab[(size_t)(rA + i * 64) * S_ + k0 + kqA]);
            cp16(&Bs[st][kB][nqB], &Vb[(size_t)(k0 + kB) * LDQKV_ + nqB]);
            CP_COMMIT();
            CP_WAIT1();
        } else {
            CP_WAIT0();
        }
        __syncthreads();
        const int st = t & 1;
        #pragma unroll
        for (int ks = 0; ks < 16; ks += 8) {
            unsigned a[2][4], bfr[4][2];
            #pragma unroll
            for (int i = 0; i < 2; i++) {
                int mB = wm + i * 16;
                a[i][0] = As[st][mB + g    ][ks + tg    ];
                a[i][1] = As[st][mB + g + 8][ks + tg    ];
                a[i][2] = As[st][mB + g    ][ks + tg + 4];
                a[i][3] = As[st][mB + g + 8][ks + tg + 4];
            }
            #pragma unroll
            for (int j = 0; j < 4; j++) {
                int nB = wn + j * 8;
                bfr[j][0] = Bs[st][ks + tg    ][nB + g];
                bfr[j][1] = Bs[st][ks + tg + 4][nB + g];
            }
            #pragma unroll
            for (int i = 0; i < 2; i++)
                #pragma unroll
                for (int j = 0; j < 4; j++)
                    mma_tf32(c[i][j], a[i][0], a[i][1], a[i][2], a[i][3], bfr[j][0], bfr[j][1]);
        }
        // normalized write-back of this stage's P tile from smem.
        // Stage st is refilled only at iter t+2 (cp issued after iter t+1's
        // barrier), so the existing one-barrier schedule covers this read.
        {
            float4 p0 = *(float4*)&As[st][rA][kqA];
            float4 p1 = *(float4*)&As[st][rA + 64][kqA];
            *(float4*)&Ab[(size_t)rA * S_ + t * 16 + kqA] =
                make_float4(p0.x * iv0, p0.y * iv0, p0.z * iv0, p0.w * iv0);
            *(float4*)&Ab[(size_t)(rA + 64) * S_ + t * 16 + kqA] =
                make_float4(p1.x * iv1, p1.y * iv1, p1.z * iv1, p1.w * iv1);
        }
    }

    float ivr[2][2];
    #pragma unroll
    for (int i = 0; i < 2; i++)
        #pragma unroll
        for (int hh = 0; hh < 2; hh++)
            ivr[i][hh] = invb[wm + i * 16 + g + hh * 8];

    #pragma unroll
    for (int i = 0; i < 2; i++)
        #pragma unroll
        for (int j = 0; j < 4; j++) {
            int col = wn + j * 8 + tg * 2;
            #pragma unroll
            for (int hh = 0; hh < 2; hh++) {
                int row = qt * 128 + wm + i * 16 + g + hh * 8;
                int t = b * S_ + row;
                *(float2*)&Ctx[(size_t)t * D_ + h * DEPTH_ + col] =
                    make_float2(roundtf(c[i][j][hh * 2 + 0] * ivr[i][hh]),
                                roundtf(c[i][j][hh * 2 + 1] * ivr[i][hh]));
            }
        }
}

// ---------------- fused residual + LayerNorm ----------------
template <int WRITE_ROUND>
__global__ void ln_residual(const float* __restrict__ a, const float* __restrict__ bb,
                            const float* __restrict__ g, const float* __restrict__ be,
                            float* __restrict__ out, float* __restrict__ outr) {
    const int t = blockIdx.x;
    const int tid = threadIdx.x;
    float4 va = ((const float4*)(a  + (size_t)t * D_))[tid];
    float4 vb = ((const float4*)(bb + (size_t)t * D_))[tid];
    float4 v = make_float4(va.x + vb.x, va.y + vb.y, va.z + vb.z, va.w + vb.w);

    __shared__ float sm[256];
    sm[tid] = v.x + v.y + v.z + v.w; __syncthreads();
    for (int st = 128; st > 0; st >>= 1) { if (tid < st) sm[tid] += sm[tid + st]; __syncthreads(); }
    const float mu = sm[0] * (1.0f / D_);
    __syncthreads();

    float dx = v.x - mu, dy = v.y - mu, dz = v.z - mu, dw = v.w - mu;
    sm[tid] = dx * dx + dy * dy + dz * dz + dw * dw; __syncthreads();
    for (int st = 128; st > 0; st >>= 1) { if (tid < st) sm[tid] += sm[tid + st]; __syncthreads(); }
    const float inv = rsqrtf(sm[0] * (1.0f / D_) + EPS_);

    float4 gg = ((const float4*)g)[tid];
    float4 bz = ((const float4*)be)[tid];
    float4 o = make_float4(dx * inv * gg.x + bz.x, dy * inv * gg.y + bz.y,
                           dz * inv * gg.z + bz.z, dw * inv * gg.w + bz.w);
    ((float4*)(out + (size_t)t * D_))[tid] = o;
    if (WRITE_ROUND) {
        float4 orr = make_float4(roundtf(o.x), roundtf(o.y), roundtf(o.z), roundtf(o.w));
        ((float4*)(outr + (size_t)t * D_))[tid] = orr;
    }
}

// ---------------- launch ----------------
extern "C" void kernel_launch(void* const* d_in, const int* in_sizes, int n_in,
                              void* d_out, int out_size) {
    const float* x  = (const float*)d_in[0];
    const float* Wq = (const float*)d_in[2];  const float* bq = (const float*)d_in[3];
    const float* Wk = (const float*)d_in[4];  const float* bk = (const float*)d_in[5];
    const float* Wv = (const float*)d_in[6];  const float* bv = (const float*)d_in[7];
    const float* Wo = (const float*)d_in[8];  const float* bo = (const float*)d_in[9];
    const float* W1 = (const float*)d_in[10]; const float* b1 = (const float*)d_in[11];
    const float* W2 = (const float*)d_in[12]; const float* b2 = (const float*)d_in[13];
    const float* ln1g = (const float*)d_in[14]; const float* ln1b = (const float*)d_in[15];
    const float* ln2g = (const float*)d_in[16]; const float* ln2b = (const float*)d_in[17];

    float* out  = (float*)d_out;
    float* attn = out + (size_t)NT_ * D_;

    float *qkv, *wcat, *bcat, *ctx, *ao, *x1, *x1r, *h1, *ff2, *xr, *wr, *rs, *inv;
    cudaGetSymbolAddress((void**)&qkv,  g_qkv);
    cudaGetSymbolAddress((void**)&wcat, g_wcat);
    cudaGetSymbolAddress((void**)&bcat, g_bcat);
    cudaGetSymbolAddress((void**)&ctx,  g_ctx);
    cudaGetSymbolAddress((void**)&ao,   g_ao);
    cudaGetSymbolAddress((void**)&x1,   g_x1);
    cudaGetSymbolAddress((void**)&x1r,  g_x1r);
    cudaGetSymbolAddress((void**)&h1,   g_h1);
    cudaGetSymbolAddress((void**)&ff2,  g_ff2);
    cudaGetSymbolAddress((void**)&xr,   g_xr);
    cudaGetSymbolAddress((void**)&wr,   g_wr);
    cudaGetSymbolAddress((void**)&rs,   g_rs);
    cudaGetSymbolAddress((void**)&inv,  g_inv);

    float* Wor = wr;
    float* W1r = wr + 1048576;
    float* W2r = wr + 5242880;

    const int GEMM_SMEM = 3 * (ASZ_ + BSZ_) * 4;       // 56832
    const int SC_SMEM   = 2 * 128 * 68 * 4;            // 69632
    cudaFuncSetAttribute(gemm_tf32p<0,1>, cudaFuncAttributeMaxDynamicSharedMemorySize, GEMM_SMEM);
    cudaFuncSetAttribute(gemm_tf32p<0,0>, cudaFuncAttributeMaxDynamicSharedMemorySize, GEMM_SMEM);
    cudaFuncSetAttribute(gemm_tf32p<1,1>, cudaFuncAttributeMaxDynamicSharedMemorySize, GEMM_SMEM);
    cudaFuncSetAttribute(attn_scores_exp, cudaFuncAttributeMaxDynamicSharedMemorySize, SC_SMEM);

    dim3 blk(256);

    round_copy_str<<<1024, blk>>>(Wq, wcat, 0);
    round_copy_str<<<1024, blk>>>(Wk, wcat, 1024);
    round_copy_str<<<1024, blk>>>(Wv, wcat, 2048);
    cudaMemcpyAsync(bcat,        bq, D_ * 4, cudaMemcpyDeviceToDevice);
    cudaMemcpyAsync(bcat + 1024, bk, D_ * 4, cudaMemcpyDeviceToDevice);
    cudaMemcpyAsync(bcat + 2048, bv, D_ * 4, cudaMemcpyDeviceToDevice);
    round_copy<<<1024, blk>>>(Wo, Wor, 262144);
    round_copy<<<4096, blk>>>(W1, W1r, 1048576);
    round_copy<<<4096, blk>>>(W2, W2r, 1048576);
    round_copy<<<4096, blk>>>(x,  xr,  1048576);

    // fused QKV: [4096,1024] @ [1024,3072]
    dim3 gQKV(LDQKV_ / 128, NT_ / 128);         // (24, 32)
    gemm_tf32p<0,1><<<gQKV, blk, GEMM_SMEM>>>(xr, wcat, bcat, qkv, NT_, LDQKV_, D_);

    dim3 gScore(S_ / 128, S_ / 128, B_ * H_);   // (16, 16, 32)
    attn_scores_exp<<<gScore, blk, SC_SMEM>>>(qkv, attn, rs);
    rowsum_inv<<<NROWS_ / 256, blk>>>(rs, inv);
    zero_upper<<<gScore, blk>>>(attn);

    dim3 gPV(S_ / 128, B_ * H_);                // (16, 32)
    attn_pv_norm<<<gPV, blk>>>(attn, qkv, inv, ctx);

    dim3 gProj(D_ / 128, NT_ / 128);            // (8, 32)
    gemm_tf32p<0,0><<<gProj, blk, GEMM_SMEM>>>(ctx, Wor, bo, ao, NT_, D_, D_);
    ln_residual<1><<<NT_, blk>>>(x, ao, ln1g, ln1b, x1, x1r);

    dim3 gFF1(DFF_ / 128, NT_ / 128);           // (32, 32)
    gemm_tf32p<1,1><<<gFF1, blk, GEMM_SMEM>>>(x1r, W1r, b1, h1, NT_, DFF_, D_);
    gemm_tf32p<0,0><<<gProj, blk, GEMM_SMEM>>>(h1, W2r, b2, ff2, NT_, D_, DFF_);
    ln_residual<0><<<NT_, blk>>>(x1, ff2, ln2g, ln2b, out, nullptr);
}

// round 9
// speedup vs baseline: 1.2027x; 1.0101x over previous
#include <cuda_runtime.h>
#include <math.h>

#define B_ 2
#define S_ 2048
#define D_ 1024
#define H_ 16
#define DEPTH_ 64
#define DFF_ 4096
#define NT_ (B_ * S_)
#define EPS_ 1e-5f
#define LDQKV_ 3072
#define NROWS_ (B_ * H_ * S_)
#define NKT_ 16

// ---------------- scratch ----------------
__device__ float g_qkv[NT_ * LDQKV_];
__device__ float g_wcat[D_ * LDQKV_];
__device__ float g_bcat[LDQKV_];
__device__ float g_ctx[NT_ * D_];
__device__ float g_ao [NT_ * D_];
__device__ float g_x1 [NT_ * D_];
__device__ float g_x1r[NT_ * D_];
__device__ float g_h1 [NT_ * DFF_];
__device__ float g_ff2[NT_ * D_];
__device__ float g_xr [NT_ * D_];
__device__ float g_wr [9437184];        // Wo(1M) W1(4M) W2(4M)
__device__ float g_rs [NROWS_ * NKT_];  // partial row sums
__device__ float g_inv[NROWS_];         // 1/rowsum

// ---------------- helpers ----------------
__device__ __forceinline__ unsigned f2tf(float x) {
    unsigned r;
    asm("cvt.rna.tf32.f32 %0, %1;" : "=r"(r) : "f"(x));
    return r;
}
__device__ __forceinline__ float roundtf(float x) { return __uint_as_float(f2tf(x)); }

__device__ __forceinline__ void mma_tf32(float c[4],
                                         unsigned a0, unsigned a1, unsigned a2, unsigned a3,
                                         unsigned b0, unsigned b1) {
    asm volatile(
        "mma.sync.aligned.m16n8k8.row.col.f32.tf32.tf32.f32 "
        "{%0,%1,%2,%3},{%4,%5,%6,%7},{%8,%9},{%0,%1,%2,%3};\n"
        : "+f"(c[0]), "+f"(c[1]), "+f"(c[2]), "+f"(c[3])
        : "r"(a0), "r"(a1), "r"(a2), "r"(a3), "r"(b0), "r"(b1));
}

__device__ __forceinline__ void cp16(void* smem, const void* gmem) {
    unsigned sa = (unsigned)__cvta_generic_to_shared(smem);
    asm volatile("cp.async.cg.shared.global [%0], [%1], 16;\n" :: "r"(sa), "l"(gmem));
}
#define CP_COMMIT() asm volatile("cp.async.commit_group;\n" ::)
#define CP_WAIT1()  asm volatile("cp.async.wait_group 1;\n" ::)
#define CP_WAIT0()  asm volatile("cp.async.wait_group 0;\n" ::)

// ---------------- rna rounding pre-passes ----------------
__global__ void round_copy(const float* __restrict__ src, float* __restrict__ dst, int n4) {
    int i = blockIdx.x * 256 + threadIdx.x;
    if (i < n4) {
        float4 t = ((const float4*)src)[i];
        t.x = roundtf(t.x); t.y = roundtf(t.y); t.z = roundtf(t.z); t.w = roundtf(t.w);
        ((float4*)dst)[i] = t;
    }
}
__global__ void round_copy_str(const float* __restrict__ src, float* __restrict__ dst, int coloff) {
    int i = blockIdx.x * 256 + threadIdx.x;
    int row = i >> 8, c4 = i & 255;
    float4 t = ((const float4*)src)[i];
    t.x = roundtf(t.x); t.y = roundtf(t.y); t.z = roundtf(t.z); t.w = roundtf(t.w);
    ((float4*)(dst + (size_t)row * LDQKV_ + coloff))[c4] = t;
}

// =====================================================================
// Dense GEMM, 3-stage cp.async, one sync per k-iter. 128x128, 8 warps.
// =====================================================================
#define ASZ_ 2560
#define BSZ_ 2176
template <int GELU, int ROUND>
__global__ __launch_bounds__(256, 2)
void gemm_tf32p(const float* __restrict__ A, const float* __restrict__ Bm,
                const float* __restrict__ bias, float* __restrict__ C,
                int M, int N, int K) {
    extern __shared__ unsigned dsm[];
    unsigned* Asp = dsm;
    unsigned* Bsp = dsm + 3 * ASZ_;

    const int tid = threadIdx.x;
    const int warp = tid >> 5, lane = tid & 31;
    const int g = lane >> 2, tg = lane & 3;
    const int m0 = blockIdx.y * 128, n0 = blockIdx.x * 128;
    const int wm = (warp >> 1) * 32, wn = (warp & 1) * 64;

    const int rA = tid >> 2,  kqA = (tid & 3) * 4;
    const int kB = tid >> 5,  nqB = (tid & 31) * 4;

    float c[2][8][4] = {};
    const int T = K >> 4;

    #pragma unroll
    for (int s = 0; s < 2; s++) {
        const int k0 = s << 4;
        #pragma unroll
        for (int i = 0; i < 2; i++)
            cp16(&Asp[s * ASZ_ + (rA + i * 64) * 20 + kqA],
                 &A[(size_t)(m0 + rA + i * 64) * K + k0 + kqA]);
        #pragma unroll
        for (int i = 0; i < 2; i++)
            cp16(&Bsp[s * BSZ_ + (kB + i * 8) * 136 + nqB],
                 &Bm[(size_t)(k0 + kB + i * 8) * N + n0 + nqB]);
        CP_COMMIT();
    }

    for (int t = 0; t < T; t++) {
        if (t + 1 < T) CP_WAIT1(); else CP_WAIT0();
        __syncthreads();
        if (t + 2 < T) {
            const int s = (t + 2) % 3, k0 = (t + 2) << 4;
            #pragma unroll
            for (int i = 0; i < 2; i++)
                cp16(&Asp[s * ASZ_ + (rA + i * 64) * 20 + kqA],
                     &A[(size_t)(m0 + rA + i * 64) * K + k0 + kqA]);
            #pragma unroll
            for (int i = 0; i < 2; i++)
                cp16(&Bsp[s * BSZ_ + (kB + i * 8) * 136 + nqB],
                     &Bm[(size_t)(k0 + kB + i * 8) * N + n0 + nqB]);
            CP_COMMIT();
        }
        const unsigned* As = Asp + (t % 3) * ASZ_;
        const unsigned* Bs = Bsp + (t % 3) * BSZ_;
        #pragma unroll
        for (int ks = 0; ks < 16; ks += 8) {
            unsigned a[2][4], b[8][2];
            #pragma unroll
            for (int i = 0; i < 2; i++) {
                int mB = wm + i * 16;
                a[i][0] = As[(mB + g    ) * 20 + ks + tg    ];
                a[i][1] = As[(mB + g + 8) * 20 + ks + tg    ];
                a[i][2] = As[(mB + g    ) * 20 + ks + tg + 4];
                a[i][3] = As[(mB + g + 8) * 20 + ks + tg + 4];
            }
            #pragma unroll
            for (int j = 0; j < 8; j++) {
                int nB = wn + j * 8;
                b[j][0] = Bs[(ks + tg    ) * 136 + nB + g];
                b[j][1] = Bs[(ks + tg + 4) * 136 + nB + g];
            }
            #pragma unroll
            for (int i = 0; i < 2; i++)
                #pragma unroll
                for (int j = 0; j < 8; j++)
                    mma_tf32(c[i][j], a[i][0], a[i][1], a[i][2], a[i][3], b[j][0], b[j][1]);
        }
    }

    #pragma unroll
    for (int i = 0; i < 2; i++) {
        #pragma unroll
        for (int j = 0; j < 8; j++) {
            int col = n0 + wn + j * 8 + tg * 2;
            float b0v = bias[col], b1v = bias[col + 1];
            #pragma unroll
            for (int h = 0; h < 2; h++) {
                int row = m0 + wm + i * 16 + g + h * 8;
                float v0 = c[i][j][h * 2 + 0] + b0v;
                float v1 = c[i][j][h * 2 + 1] + b1v;
                if (GELU) {
                    v0 = 0.5f * v0 * (1.0f + erff(v0 * 0.70710678118654752f));
                    v1 = 0.5f * v1 * (1.0f + erff(v1 * 0.70710678118654752f));
                }
                if (ROUND) { v0 = roundtf(v0); v1 = roundtf(v1); }
                *(float2*)&C[(size_t)row * N + col] = make_float2(v0, v1);
            }
        }
    }
}

// =====================================================================
// Scores + exp + partial row sums; kt>qt blocks zero-fill their tile
// (folded zero_upper — writes overlap compute blocks' MMA).
// Dyn smem 2*128*68*4 = 69632 B.
// =====================================================================
__global__ __launch_bounds__(256, 2)
void attn_scores_exp(const float* __restrict__ QKV, float* __restrict__ attnP,
                     float* __restrict__ rs) {
    const int kt = blockIdx.x, qt = blockIdx.y, bh = blockIdx.z;
    const int tid = threadIdx.x;

    if (kt > qt) {
        float4 z = make_float4(0.f, 0.f, 0.f, 0.f);
        float* tb = attnP + ((size_t)bh * S_ + qt * 128) * S_ + kt * 128;
        #pragma unroll
        for (int e = 0; e < 16; e++) {
            int u = tid + e * 256;
            int r = u >> 5, c4 = u & 31;
            ((float4*)(tb + (size_t)r * S_))[c4] = z;
        }
        return;
    }

    const int b = bh >> 4, h = bh & 15;

    extern __shared__ unsigned dsm[];
    unsigned* Qs = dsm;              // [128][68]
    unsigned* Ks = dsm + 128 * 68;

    const int warp = tid >> 5, lane = tid & 31;
    const int g = lane >> 2, tg = lane & 3;
    const int wm = (warp >> 1) * 32, wn = (warp & 1) * 64;

    const float* qb = QKV + (size_t)(b * S_ + qt * 128) * LDQKV_ + h * DEPTH_;
    const float* kb = QKV + (size_t)(b * S_ + kt * 128) * LDQKV_ + 1024 + h * DEPTH_;

    #pragma unroll
    for (int e = 0; e < 8; e++) {
        int u = tid + e * 256;
        int r = u >> 4, cc = (u & 15) * 4;
        cp16(&Qs[r * 68 + cc], &qb[(size_t)r * LDQKV_ + cc]);
        cp16(&Ks[r * 68 + cc], &kb[(size_t)r * LDQKV_ + cc]);
    }
    CP_COMMIT();
    CP_WAIT0();
    __syncthreads();

    float c[2][8][4] = {};
    #pragma unroll
    for (int ks = 0; ks < 64; ks += 8) {
        unsigned a[2][4], bfr[8][2];
        #pragma unroll
        for (int i = 0; i < 2; i++) {
            int mB = wm + i * 16;
            a[i][0] = Qs[(mB + g    ) * 68 + ks + tg    ];
            a[i][1] = Qs[(mB + g + 8) * 68 + ks + tg    ];
            a[i][2] = Qs[(mB + g    ) * 68 + ks + tg + 4];
            a[i][3] = Qs[(mB + g + 8) * 68 + ks + tg + 4];
        }
        #pragma unroll
        for (int j = 0; j < 8; j++) {
            int nB = wn + j * 8;
            bfr[j][0] = Ks[(nB + g) * 68 + ks + tg    ];
            bfr[j][1] = Ks[(nB + g) * 68 + ks + tg + 4];
        }
        #pragma unroll
        for (int i = 0; i < 2; i++)
            #pragma unroll
            for (int j = 0; j < 8; j++)
                mma_tf32(c[i][j], a[i][0], a[i][1], a[i][2], a[i][3], bfr[j][0], bfr[j][1]);
    }

    const bool diag = (kt == qt);
    float rsum[2][2] = {};
    float* ob = attnP + ((size_t)bh * S_ + qt * 128) * S_ + kt * 128;
    #pragma unroll
    for (int i = 0; i < 2; i++)
        #pragma unroll
        for (int j = 0; j < 8; j++) {
            int col = wn + j * 8 + tg * 2;
            #pragma unroll
            for (int hh = 0; hh < 2; hh++) {
                int row = wm + i * 16 + g + hh * 8;
                float v0 = __expf(c[i][j][hh * 2 + 0] * 0.03125f);
                float v1 = __expf(c[i][j][hh * 2 + 1] * 0.03125f);
                if (diag) {
                    if (col     > row) v0 = 0.f;
                    if (col + 1 > row) v1 = 0.f;
                }
                rsum[i][hh] += v0 + v1;
                *(float2*)&ob[(size_t)row * S_ + col] = make_float2(v0, v1);
            }
        }

    #pragma unroll
    for (int i = 0; i < 2; i++)
        #pragma unroll
        for (int hh = 0; hh < 2; hh++) {
            rsum[i][hh] += __shfl_xor_sync(0xffffffff, rsum[i][hh], 1);
            rsum[i][hh] += __shfl_xor_sync(0xffffffff, rsum[i][hh], 2);
        }
    __syncthreads();
    float* psm = (float*)Qs;
    if (tg == 0) {
        #pragma unroll
        for (int i = 0; i < 2; i++)
            #pragma unroll
            for (int hh = 0; hh < 2; hh++)
                psm[(wm + i * 16 + g + hh * 8) * 2 + (wn >> 6)] = rsum[i][hh];
    }
    __syncthreads();
    if (tid < 128)
        rs[((size_t)bh * S_ + qt * 128 + tid) * NKT_ + kt] = psm[tid * 2] + psm[tid * 2 + 1];
}

// ---------------- inv[row] = 1 / sum of valid partials ----------------
__global__ void rowsum_inv(const float* __restrict__ rs, float* __restrict__ inv) {
    int row = blockIdx.x * 256 + threadIdx.x;
    int qt = (row & (S_ - 1)) >> 7;
    float s = 0.f;
    for (int kt = 0; kt <= qt; kt++) s += rs[(size_t)row * NKT_ + kt];
    inv[row] = 1.0f / s;
}

// =====================================================================
// ctx = (P' @ V) * inv; normalized attn written back FROM SMEM in-loop.
// Longest-first: qt = NKT_-1 - blockIdx.x.
// =====================================================================
__global__ __launch_bounds__(256, 2)
void attn_pv_norm(float* __restrict__ attnP, const float* __restrict__ QKV,
                  const float* __restrict__ inv, float* __restrict__ Ctx) {
    const int qt = NKT_ - 1 - blockIdx.x, bh = blockIdx.y;
    const int b = bh >> 4, h = bh & 15;

    __shared__ unsigned As[2][128][20];
    __shared__ unsigned Bs[2][16][72];

    const int tid = threadIdx.x;
    const int warp = tid >> 5, lane = tid & 31;
    const int g = lane >> 2, tg = lane & 3;
    const int wm = (warp >> 1) * 32, wn = (warp & 1) * 32;

    float* Ab = attnP + ((size_t)bh * S_ + qt * 128) * S_;
    const float* Vb = QKV + (size_t)(b * S_) * LDQKV_ + 2048 + h * DEPTH_;
    const float* invb = inv + (size_t)bh * S_ + qt * 128;

    const int rA = tid >> 2, kqA = (tid & 3) * 4;
    const int kB = tid >> 4, nqB = (tid & 15) * 4;

    const float iv0 = invb[rA], iv1 = invb[rA + 64];

    float c[2][4][4] = {};
    const int T = (qt + 1) * 8;

    #pragma unroll
    for (int i = 0; i < 2; i++)
        cp16(&As[0][rA + i * 64][kqA], &Ab[(size_t)(rA + i * 64) * S_ + kqA]);
    cp16(&Bs[0][kB][nqB], &Vb[(size_t)kB * LDQKV_ + nqB]);
    CP_COMMIT();

    for (int t = 0; t < T; t++) {
        if (t + 1 < T) {
            const int k0 = (t + 1) << 4, st = (t + 1) & 1;
            #pragma unroll
            for (int i = 0; i < 2; i++)
                cp16(&As[st][rA + i * 64][kqA], &Ab[(size_t)(rA + i * 64) * S_ + k0 + kqA]);
            cp16(&Bs[st][kB][nqB], &Vb[(size_t)(k0 + kB) * LDQKV_ + nqB]);
            CP_COMMIT();
            CP_WAIT1();
        } else {
            CP_WAIT0();
        }
        __syncthreads();
        const int st = t & 1;
        #pragma unroll
        for (int ks = 0; ks < 16; ks += 8) {
            unsigned a[2][4], bfr[4][2];
            #pragma unroll
            for (int i = 0; i < 2; i++) {
                int mB = wm + i * 16;
                a[i][0] = As[st][mB + g    ][ks + tg    ];
                a[i][1] = As[st][mB + g + 8][ks + tg    ];
                a[i][2] = As[st][mB + g    ][ks + tg + 4];
                a[i][3] = As[st][mB + g + 8][ks + tg + 4];
            }
            #pragma unroll
            for (int j = 0; j < 4; j++) {
                int nB = wn + j * 8;
                bfr[j][0] = Bs[st][ks + tg    ][nB + g];
                bfr[j][1] = Bs[st][ks + tg + 4][nB + g];
            }
            #pragma unroll
            for (int i = 0; i < 2; i++)
                #pragma unroll
                for (int j = 0; j < 4; j++)
                    mma_tf32(c[i][j], a[i][0], a[i][1], a[i][2], a[i][3], bfr[j][0], bfr[j][1]);
        }
        // normalized write-back of this stage's P tile from smem
        {
            float4 p0 = *(float4*)&As[st][rA][kqA];
            float4 p1 = *(float4*)&As[st][rA + 64][kqA];
            *(float4*)&Ab[(size_t)rA * S_ + t * 16 + kqA] =
                make_float4(p0.x * iv0, p0.y * iv0, p0.z * iv0, p0.w * iv0);
            *(float4*)&Ab[(size_t)(rA + 64) * S_ + t * 16 + kqA] =
                make_float4(p1.x * iv1, p1.y * iv1, p1.z * iv1, p1.w * iv1);
        }
    }

    float ivr[2][2];
    #pragma unroll
    for (int i = 0; i < 2; i++)
        #pragma unroll
        for (int hh = 0; hh < 2; hh++)
            ivr[i][hh] = invb[wm + i * 16 + g + hh * 8];

    #pragma unroll
    for (int i = 0; i < 2; i++)
        #pragma unroll
        for (int j = 0; j < 4; j++) {
            int col = wn + j * 8 + tg * 2;
            #pragma unroll
            for (int hh = 0; hh < 2; hh++) {
                int row = qt * 128 + wm + i * 16 + g + hh * 8;
                int t = b * S_ + row;
                *(float2*)&Ctx[(size_t)t * D_ + h * DEPTH_ + col] =
                    make_float2(roundtf(c[i][j][hh * 2 + 0] * ivr[i][hh]),
                                roundtf(c[i][j][hh * 2 + 1] * ivr[i][hh]));
            }
        }
}

// ---------------- fused residual + LayerNorm ----------------
template <int WRITE_ROUND>
__global__ void ln_residual(const float* __restrict__ a, const float* __restrict__ bb,
                            const float* __restrict__ g, const float* __restrict__ be,
                            float* __restrict__ out, float* __restrict__ outr) {
    const int t = blockIdx.x;
    const int tid = threadIdx.x;
    float4 va = ((const float4*)(a  + (size_t)t * D_))[tid];
    float4 vb = ((const float4*)(bb + (size_t)t * D_))[tid];
    float4 v = make_float4(va.x + vb.x, va.y + vb.y, va.z + vb.z, va.w + vb.w);

    __shared__ float sm[256];
    sm[tid] = v.x + v.y + v.z + v.w; __syncthreads();
    for (int st = 128; st > 0; st >>= 1) { if (tid < st) sm[tid] += sm[tid + st]; __syncthreads(); }
    const float mu = sm[0] * (1.0f / D_);
    __syncthreads();

    float dx = v.x - mu, dy = v.y - mu, dz = v.z - mu, dw = v.w - mu;
    sm[tid] = dx * dx + dy * dy + dz * dz + dw * dw; __syncthreads();
    for (int st = 128; st > 0; st >>= 1) { if (tid < st) sm[tid] += sm[tid + st]; __syncthreads(); }
    const float inv = rsqrtf(sm[0] * (1.0f / D_) + EPS_);

    float4 gg = ((const float4*)g)[tid];
    float4 bz = ((const float4*)be)[tid];
    float4 o = make_float4(dx * inv * gg.x + bz.x, dy * inv * gg.y + bz.y,
                           dz * inv * gg.z + bz.z, dw * inv * gg.w + bz.w);
    ((float4*)(out + (size_t)t * D_))[tid] = o;
    if (WRITE_ROUND) {
        float4 orr = make_float4(roundtf(o.x), roundtf(o.y), roundtf(o.z), roundtf(o.w));
        ((float4*)(outr + (size_t)t * D_))[tid] = orr;
    }
}

// ---------------- launch ----------------
extern "C" void kernel_launch(void* const* d_in, const int* in_sizes, int n_in,
                              void* d_out, int out_size) {
    const float* x  = (const float*)d_in[0];
    const float* Wq = (const float*)d_in[2];  const float* bq = (const float*)d_in[3];
    const float* Wk = (const float*)d_in[4];  const float* bk = (const float*)d_in[5];
    const float* Wv = (const float*)d_in[6];  const float* bv = (const float*)d_in[7];
    const float* Wo = (const float*)d_in[8];  const float* bo = (const float*)d_in[9];
    const float* W1 = (const float*)d_in[10]; const float* b1 = (const float*)d_in[11];
    const float* W2 = (const float*)d_in[12]; const float* b2 = (const float*)d_in[13];
    const float* ln1g = (const float*)d_in[14]; const float* ln1b = (const float*)d_in[15];
    const float* ln2g = (const float*)d_in[16]; const float* ln2b = (const float*)d_in[17];

    float* out  = (float*)d_out;
    float* attn = out + (size_t)NT_ * D_;

    float *qkv, *wcat, *bcat, *ctx, *ao, *x1, *x1r, *h1, *ff2, *xr, *wr, *rs, *inv;
    cudaGetSymbolAddress((void**)&qkv,  g_qkv);
    cudaGetSymbolAddress((void**)&wcat, g_wcat);
    cudaGetSymbolAddress((void**)&bcat, g_bcat);
    cudaGetSymbolAddress((void**)&ctx,  g_ctx);
    cudaGetSymbolAddress((void**)&ao,   g_ao);
    cudaGetSymbolAddress((void**)&x1,   g_x1);
    cudaGetSymbolAddress((void**)&x1r,  g_x1r);
    cudaGetSymbolAddress((void**)&h1,   g_h1);
    cudaGetSymbolAddress((void**)&ff2,  g_ff2);
    cudaGetSymbolAddress((void**)&xr,   g_xr);
    cudaGetSymbolAddress((void**)&wr,   g_wr);
    cudaGetSymbolAddress((void**)&rs,   g_rs);
    cudaGetSymbolAddress((void**)&inv,  g_inv);

    float* Wor = wr;
    float* W1r = wr + 1048576;
    float* W2r = wr + 5242880;

    const int GEMM_SMEM = 3 * (ASZ_ + BSZ_) * 4;       // 56832
    const int SC_SMEM   = 2 * 128 * 68 * 4;            // 69632
    cudaFuncSetAttribute(gemm_tf32p<0,1>, cudaFuncAttributeMaxDynamicSharedMemorySize, GEMM_SMEM);
    cudaFuncSetAttribute(gemm_tf32p<0,0>, cudaFuncAttributeMaxDynamicSharedMemorySize, GEMM_SMEM);
    cudaFuncSetAttribute(gemm_tf32p<1,1>, cudaFuncAttributeMaxDynamicSharedMemorySize, GEMM_SMEM);
    cudaFuncSetAttribute(attn_scores_exp, cudaFuncAttributeMaxDynamicSharedMemorySize, SC_SMEM);

    dim3 blk(256);

    round_copy_str<<<1024, blk>>>(Wq, wcat, 0);
    round_copy_str<<<1024, blk>>>(Wk, wcat, 1024);
    round_copy_str<<<1024, blk>>>(Wv, wcat, 2048);
    cudaMemcpyAsync(bcat,        bq, D_ * 4, cudaMemcpyDeviceToDevice);
    cudaMemcpyAsync(bcat + 1024, bk, D_ * 4, cudaMemcpyDeviceToDevice);
    cudaMemcpyAsync(bcat + 2048, bv, D_ * 4, cudaMemcpyDeviceToDevice);
    round_copy<<<1024, blk>>>(Wo, Wor, 262144);
    round_copy<<<4096, blk>>>(W1, W1r, 1048576);
    round_copy<<<4096, blk>>>(W2, W2r, 1048576);
    round_copy<<<4096, blk>>>(x,  xr,  1048576);

    // fused QKV: [4096,1024] @ [1024,3072]
    dim3 gQKV(LDQKV_ / 128, NT_ / 128);         // (24, 32)
    gemm_tf32p<0,1><<<gQKV, blk, GEMM_SMEM>>>(xr, wcat, bcat, qkv, NT_, LDQKV_, D_);

    dim3 gScore(S_ / 128, S_ / 128, B_ * H_);   // (16, 16, 32)
    attn_scores_exp<<<gScore, blk, SC_SMEM>>>(qkv, attn, rs);
    rowsum_inv<<<NROWS_ / 256, blk>>>(rs, inv);

    dim3 gPV(S_ / 128, B_ * H_);                // (16, 32)
    attn_pv_norm<<<gPV, blk>>>(attn, qkv, inv, ctx);

    dim3 gProj(D_ / 128, NT_ / 128);            // (8, 32)
    gemm_tf32p<0,0><<<gProj, blk, GEMM_SMEM>>>(ctx, Wor, bo, ao, NT_, D_, D_);
    ln_residual<1><<<NT_, blk>>>(x, ao, ln1g, ln1b, x1, x1r);

    dim3 gFF1(DFF_ / 128, NT_ / 128);           // (32, 32)
    gemm_tf32p<1,1><<<gFF1, blk, GEMM_SMEM>>>(x1r, W1r, b1, h1, NT_, DFF_, D_);
    gemm_tf32p<0,0><<<gProj, blk, GEMM_SMEM>>>(h1, W2r, b2, ff2, NT_, D_, DFF_);
    ln_residual<0><<<NT_, blk>>>(x1, ff2, ln2g, ln2b, out, nullptr);
}

// round 10
// speedup vs baseline: 1.2410x; 1.0319x over previous
#include <cuda_runtime.h>
#include <math.h>
#include <stdint.h>

#define B_ 2
#define S_ 2048
#define D_ 1024
#define H_ 16
#define DEPTH_ 64
#define DFF_ 4096
#define NT_ (B_ * S_)
#define EPS_ 1e-5f
#define LDQKV_ 3072
#define NROWS_ (B_ * H_ * S_)
#define NKT_ 16

// ---------------- scratch ----------------
__device__ float g_qkv[NT_ * LDQKV_];
__device__ float g_wcat[D_ * LDQKV_];   // WqkvT [3072][1024]
__device__ float g_bcat[LDQKV_];
__device__ float g_ctx[NT_ * D_];
__device__ float g_ao [NT_ * D_];
__device__ float g_x1 [NT_ * D_];
__device__ float g_x1r[NT_ * D_];
__device__ float g_h1 [NT_ * DFF_];
__device__ float g_ff2[NT_ * D_];
__device__ float g_xr [NT_ * D_];
__device__ float g_wr [9437184];        // WoT(1M) W1T(4M) W2T(4M)
__device__ float g_rs [NROWS_ * NKT_];
__device__ float g_inv[NROWS_];

// ---------------- helpers ----------------
__device__ __forceinline__ unsigned f2tf(float x) {
    unsigned r;
    asm("cvt.rna.tf32.f32 %0, %1;" : "=r"(r) : "f"(x));
    return r;
}
__device__ __forceinline__ float roundtf(float x) { return __uint_as_float(f2tf(x)); }

__device__ __forceinline__ void mma_tf32(float c[4],
                                         unsigned a0, unsigned a1, unsigned a2, unsigned a3,
                                         unsigned b0, unsigned b1) {
    asm volatile(
        "mma.sync.aligned.m16n8k8.row.col.f32.tf32.tf32.f32 "
        "{%0,%1,%2,%3},{%4,%5,%6,%7},{%8,%9},{%0,%1,%2,%3};\n"
        : "+f"(c[0]), "+f"(c[1]), "+f"(c[2]), "+f"(c[3])
        : "r"(a0), "r"(a1), "r"(a2), "r"(a3), "r"(b0), "r"(b1));
}

__device__ __forceinline__ void ldsm_x4(unsigned &r0, unsigned &r1, unsigned &r2, unsigned &r3,
                                        uint32_t addr) {
    asm volatile("ldmatrix.sync.aligned.m8n8.x4.shared.b16 {%0,%1,%2,%3}, [%4];"
                 : "=r"(r0), "=r"(r1), "=r"(r2), "=r"(r3) : "r"(addr));
}

__device__ __forceinline__ void cp16(void* smem, const void* gmem) {
    unsigned sa = (unsigned)__cvta_generic_to_shared(smem);
    asm volatile("cp.async.cg.shared.global [%0], [%1], 16;\n" :: "r"(sa), "l"(gmem));
}
#define CP_COMMIT() asm volatile("cp.async.commit_group;\n" ::)
#define CP_WAIT1()  asm volatile("cp.async.wait_group 1;\n" ::)
#define CP_WAIT0()  asm volatile("cp.async.wait_group 0;\n" ::)

__device__ __forceinline__ uint32_t smem_u32(const void* p) {
    return (uint32_t)__cvta_generic_to_shared(p);
}

// ---------------- pre-passes ----------------
__global__ void round_copy(const float* __restrict__ src, float* __restrict__ dst, int n4) {
    int i = blockIdx.x * 256 + threadIdx.x;
    if (i < n4) {
        float4 t = ((const float4*)src)[i];
        t.x = roundtf(t.x); t.y = roundtf(t.y); t.z = roundtf(t.z); t.w = roundtf(t.w);
        ((float4*)dst)[i] = t;
    }
}
// dst[c][r] = roundtf(src[r][c]); src R x C. block (32,8), grid (C/32, R/32)
__global__ void round_T(const float* __restrict__ src, float* __restrict__ dst, int R, int C) {
    __shared__ float t[32][33];
    int c0 = blockIdx.x * 32, r0 = blockIdx.y * 32;
    int tx = threadIdx.x, ty = threadIdx.y;
    #pragma unroll
    for (int i = 0; i < 4; i++)
        t[ty + i * 8][tx] = src[(size_t)(r0 + ty + i * 8) * C + c0 + tx];
    __syncthreads();
    #pragma unroll
    for (int i = 0; i < 4; i++)
        dst[(size_t)(c0 + ty + i * 8) * R + r0 + tx] = roundtf(t[tx][ty + i * 8]);
}

// =====================================================================
// Dense GEMM: C = A[M,K] @ Bt[N,K]^T + bias. Both operands K-major rows.
// 3-stage cp.async, 128x128 tile, 8 warps, ldmatrix fragment loads.
// Stage = (128*20 + 128*20) u32; 3 stages = 61440 B.
// =====================================================================
#define ASZ_ 2560
#define BSZ_ 2560
template <int GELU, int ROUND>
__global__ __launch_bounds__(256, 2)
void gemm_tf32p(const float* __restrict__ A, const float* __restrict__ Bt,
                const float* __restrict__ bias, float* __restrict__ C,
                int M, int N, int K) {
    extern __shared__ unsigned dsm[];
    unsigned* Asp = dsm;
    unsigned* Bsp = dsm + 3 * ASZ_;
    const uint32_t sA0 = smem_u32(Asp), sB0 = smem_u32(Bsp);

    const int tid = threadIdx.x;
    const int warp = tid >> 5, lane = tid & 31;
    const int g = lane >> 2, tg = lane & 3;
    const int m0 = blockIdx.y * 128, n0 = blockIdx.x * 128;
    const int wm = (warp >> 1) * 32, wn = (warp & 1) * 64;

    // ldmatrix address components
    const int a_row = wm + (lane & 15);
    const int a_col = (lane >> 4) * 4;
    const int b_row = (lane & 7) + ((lane >> 4) & 1) * 8;
    const int b_col = ((lane >> 3) & 1) * 4;

    const int rL = tid >> 2, kqL = (tid & 3) * 4;     // loader indices

    float c[2][8][4] = {};
    const int T = K >> 4;

    #pragma unroll
    for (int s = 0; s < 2; s++) {
        const int k0 = s << 4;
        #pragma unroll
        for (int i = 0; i < 2; i++) {
            cp16(&Asp[s * ASZ_ + (rL + i * 64) * 20 + kqL],
                 &A[(size_t)(m0 + rL + i * 64) * K + k0 + kqL]);
            cp16(&Bsp[s * BSZ_ + (rL + i * 64) * 20 + kqL],
                 &Bt[(size_t)(n0 + rL + i * 64) * K + k0 + kqL]);
        }
        CP_COMMIT();
    }

    for (int t = 0; t < T; t++) {
        if (t + 1 < T) CP_WAIT1(); else CP_WAIT0();
        __syncthreads();
        if (t + 2 < T) {
            const int s = (t + 2) % 3, k0 = (t + 2) << 4;
            #pragma unroll
            for (int i = 0; i < 2; i++) {
                cp16(&Asp[s * ASZ_ + (rL + i * 64) * 20 + kqL],
                     &A[(size_t)(m0 + rL + i * 64) * K + k0 + kqL]);
                cp16(&Bsp[s * BSZ_ + (rL + i * 64) * 20 + kqL],
                     &Bt[(size_t)(n0 + rL + i * 64) * K + k0 + kqL]);
            }
            CP_COMMIT();
        }
        const uint32_t sA = sA0 + (t % 3) * ASZ_ * 4;
        const uint32_t sB = sB0 + (t % 3) * BSZ_ * 4;
        #pragma unroll
        for (int ks = 0; ks < 16; ks += 8) {
            unsigned a[2][4], b[8][2];
            #pragma unroll
            for (int i = 0; i < 2; i++)
                ldsm_x4(a[i][0], a[i][1], a[i][2], a[i][3],
                        sA + (uint32_t)(((a_row + i * 16) * 20 + ks + a_col) * 4));
            #pragma unroll
            for (int jj = 0; jj < 4; jj++)
                ldsm_x4(b[2 * jj][0], b[2 * jj][1], b[2 * jj + 1][0], b[2 * jj + 1][1],
                        sB + (uint32_t)(((wn + jj * 16 + b_row) * 20 + ks + b_col) * 4));
            #pragma unroll
            for (int i = 0; i < 2; i++)
                #pragma unroll
                for (int j = 0; j < 8; j++)
                    mma_tf32(c[i][j], a[i][0], a[i][1], a[i][2], a[i][3], b[j][0], b[j][1]);
        }
    }

    #pragma unroll
    for (int i = 0; i < 2; i++) {
        #pragma unroll
        for (int j = 0; j < 8; j++) {
            int col = n0 + wn + j * 8 + tg * 2;
            float b0v = bias[col], b1v = bias[col + 1];
            #pragma unroll
            for (int h = 0; h < 2; h++) {
                int row = m0 + wm + i * 16 + g + h * 8;
                float v0 = c[i][j][h * 2 + 0] + b0v;
                float v1 = c[i][j][h * 2 + 1] + b1v;
                if (GELU) {
                    v0 = 0.5f * v0 * (1.0f + erff(v0 * 0.70710678118654752f));
                    v1 = 0.5f * v1 * (1.0f + erff(v1 * 0.70710678118654752f));
                }
                if (ROUND) { v0 = roundtf(v0); v1 = roundtf(v1); }
                *(float2*)&C[(size_t)row * N + col] = make_float2(v0, v1);
            }
        }
    }
}

// =====================================================================
// Scores + exp + partial row sums; kt>qt blocks zero-fill.
// ldmatrix fragment loads for Q and K (both K-major rows, stride 68).
// =====================================================================
__global__ __launch_bounds__(256, 2)
void attn_scores_exp(const float* __restrict__ QKV, float* __restrict__ attnP,
                     float* __restrict__ rs) {
    const int kt = blockIdx.x, qt = blockIdx.y, bh = blockIdx.z;
    const int tid = threadIdx.x;

    if (kt > qt) {
        float4 z = make_float4(0.f, 0.f, 0.f, 0.f);
        float* tb = attnP + ((size_t)bh * S_ + qt * 128) * S_ + kt * 128;
        #pragma unroll
        for (int e = 0; e < 16; e++) {
            int u = tid + e * 256;
            int r = u >> 5, c4 = u & 31;
            ((float4*)(tb + (size_t)r * S_))[c4] = z;
        }
        return;
    }

    const int b = bh >> 4, h = bh & 15;

    extern __shared__ unsigned dsm[];
    unsigned* Qs = dsm;              // [128][68]
    unsigned* Ks = dsm + 128 * 68;
    const uint32_t sQ = smem_u32(Qs), sK = smem_u32(Ks);

    const int warp = tid >> 5, lane = tid & 31;
    const int g = lane >> 2, tg = lane & 3;
    const int wm = (warp >> 1) * 32, wn = (warp & 1) * 64;

    const int a_row = wm + (lane & 15);
    const int a_col = (lane >> 4) * 4;
    const int b_row = (lane & 7) + ((lane >> 4) & 1) * 8;
    const int b_col = ((lane >> 3) & 1) * 4;

    const float* qb = QKV + (size_t)(b * S_ + qt * 128) * LDQKV_ + h * DEPTH_;
    const float* kb = QKV + (size_t)(b * S_ + kt * 128) * LDQKV_ + 1024 + h * DEPTH_;

    #pragma unroll
    for (int e = 0; e < 8; e++) {
        int u = tid + e * 256;
        int r = u >> 4, cc = (u & 15) * 4;
        cp16(&Qs[r * 68 + cc], &qb[(size_t)r * LDQKV_ + cc]);
        cp16(&Ks[r * 68 + cc], &kb[(size_t)r * LDQKV_ + cc]);
    }
    CP_COMMIT();
    CP_WAIT0();
    __syncthreads();

    float c[2][8][4] = {};
    #pragma unroll
    for (int ks = 0; ks < 64; ks += 8) {
        unsigned a[2][4], bfr[8][2];
        #pragma unroll
        for (int i = 0; i < 2; i++)
            ldsm_x4(a[i][0], a[i][1], a[i][2], a[i][3],
                    sQ + (uint32_t)(((a_row + i * 16) * 68 + ks + a_col) * 4));
        #pragma unroll
        for (int jj = 0; jj < 4; jj++)
            ldsm_x4(bfr[2 * jj][0], bfr[2 * jj][1], bfr[2 * jj + 1][0], bfr[2 * jj + 1][1],
                    sK + (uint32_t)(((wn + jj * 16 + b_row) * 68 + ks + b_col) * 4));
        #pragma unroll
        for (int i = 0; i < 2; i++)
            #pragma unroll
            for (int j = 0; j < 8; j++)
                mma_tf32(c[i][j], a[i][0], a[i][1], a[i][2], a[i][3], bfr[j][0], bfr[j][1]);
    }

    const bool diag = (kt == qt);
    float rsum[2][2] = {};
    float* ob = attnP + ((size_t)bh * S_ + qt * 128) * S_ + kt * 128;
    #pragma unroll
    for (int i = 0; i < 2; i++)
        #pragma unroll
        for (int j = 0; j < 8; j++) {
            int col = wn + j * 8 + tg * 2;
            #pragma unroll
            for (int hh = 0; hh < 2; hh++) {
                int row = wm + i * 16 + g + hh * 8;
                float v0 = __expf(c[i][j][hh * 2 + 0] * 0.03125f);
                float v1 = __expf(c[i][j][hh * 2 + 1] * 0.03125f);
                if (diag) {
                    if (col     > row) v0 = 0.f;
                    if (col + 1 > row) v1 = 0.f;
                }
                rsum[i][hh] += v0 + v1;
                *(float2*)&ob[(size_t)row * S_ + col] = make_float2(v0, v1);
            }
        }

    #pragma unroll
    for (int i = 0; i < 2; i++)
        #pragma unroll
        for (int hh = 0; hh < 2; hh++) {
            rsum[i][hh] += __shfl_xor_sync(0xffffffff, rsum[i][hh], 1);
            rsum[i][hh] += __shfl_xor_sync(0xffffffff, rsum[i][hh], 2);
        }
    __syncthreads();
    float* psm = (float*)Qs;
    if (tg == 0) {
        #pragma unroll
        for (int i = 0; i < 2; i++)
            #pragma unroll
            for (int hh = 0; hh < 2; hh++)
                psm[(wm + i * 16 + g + hh * 8) * 2 + (wn >> 6)] = rsum[i][hh];
    }
    __syncthreads();
    if (tid < 128)
        rs[((size_t)bh * S_ + qt * 128 + tid) * NKT_ + kt] = psm[tid * 2] + psm[tid * 2 + 1];
}

// ---------------- inv[row] = 1 / sum of valid partials ----------------
__global__ void rowsum_inv(const float* __restrict__ rs, float* __restrict__ inv) {
    int row = blockIdx.x * 256 + threadIdx.x;
    int qt = (row & (S_ - 1)) >> 7;
    float s = 0.f;
    for (int kt = 0; kt <= qt; kt++) s += rs[(size_t)row * NKT_ + kt];
    inv[row] = 1.0f / s;
}

// =====================================================================
// ctx = (P' @ V) * inv; normalized attn written back FROM SMEM in-loop.
// Longest-first qt; A-frags via ldmatrix, V-frags via LDS.
// =====================================================================
__global__ __launch_bounds__(256, 2)
void attn_pv_norm(float* __restrict__ attnP, const float* __restrict__ QKV,
                  const float* __restrict__ inv, float* __restrict__ Ctx) {
    const int qt = NKT_ - 1 - blockIdx.x, bh = blockIdx.y;
    const int b = bh >> 4, h = bh & 15;

    __shared__ unsigned As[2][128][20];
    __shared__ unsigned Bs[2][16][72];
    const uint32_t sAbase = smem_u32(&As[0][0][0]);

    const int tid = threadIdx.x;
    const int warp = tid >> 5, lane = tid & 31;
    const int g = lane >> 2, tg = lane & 3;
    const int wm = (warp >> 1) * 32, wn = (warp & 1) * 32;

    const int a_row = wm + (lane & 15);
    const int a_col = (lane >> 4) * 4;

    float* Ab = attnP + ((size_t)bh * S_ + qt * 128) * S_;
    const float* Vb = QKV + (size_t)(b * S_) * LDQKV_ + 2048 + h * DEPTH_;
    const float* invb = inv + (size_t)bh * S_ + qt * 128;

    const int rA = tid >> 2, kqA = (tid & 3) * 4;
    const int kB = tid >> 4, nqB = (tid & 15) * 4;

    const float iv0 = invb[rA], iv1 = invb[rA + 64];

    float c[2][4][4] = {};
    const int T = (qt + 1) * 8;

    #pragma unroll
    for (int i = 0; i < 2; i++)
        cp16(&As[0][rA + i * 64][kqA], &Ab[(size_t)(rA + i * 64) * S_ + kqA]);
    cp16(&Bs[0][kB][nqB], &Vb[(size_t)kB * LDQKV_ + nqB]);
    CP_COMMIT();

    for (int t = 0; t < T; t++) {
        if (t + 1 < T) {
            const int k0 = (t + 1) << 4, st = (t + 1) & 1;
            #pragma unroll
            for (int i = 0; i < 2; i++)
                cp16(&As[st][rA + i * 64][kqA], &Ab[(size_t)(rA + i * 64) * S_ + k0 + kqA]);
            cp16(&Bs[st][kB][nqB], &Vb[(size_t)(k0 + kB) * LDQKV_ + nqB]);
            CP_COMMIT();
            CP_WAIT1();
        } else {
            CP_WAIT0();
        }
        __syncthreads();
        const int st = t & 1;
        const uint32_t sA = sAbase + (uint32_t)(st * 128 * 20 * 4);
        #pragma unroll
        for (int ks = 0; ks < 16; ks += 8) {
            unsigned a[2][4], bfr[4][2];
            #pragma unroll
            for (int i = 0; i < 2; i++)
                ldsm_x4(a[i][0], a[i][1], a[i][2], a[i][3],
                        sA + (uint32_t)(((a_row + i * 16) * 20 + ks + a_col) * 4));
            #pragma unroll
            for (int j = 0; j < 4; j++) {
                int nB = wn + j * 8;
                bfr[j][0] = Bs[st][ks + tg    ][nB + g];
                bfr[j][1] = Bs[st][ks + tg + 4][nB + g];
            }
            #pragma unroll
            for (int i = 0; i < 2; i++)
                #pragma unroll
                for (int j = 0; j < 4; j++)
                    mma_tf32(c[i][j], a[i][0], a[i][1], a[i][2], a[i][3], bfr[j][0], bfr[j][1]);
        }
        // normalized write-back of this stage's P tile from smem
        {
            float4 p0 = *(float4*)&As[st][rA][kqA];
            float4 p1 = *(float4*)&As[st][rA + 64][kqA];
            *(float4*)&Ab[(size_t)rA * S_ + t * 16 + kqA] =
                make_float4(p0.x * iv0, p0.y * iv0, p0.z * iv0, p0.w * iv0);
            *(float4*)&Ab[(size_t)(rA + 64) * S_ + t * 16 + kqA] =
                make_float4(p1.x * iv1, p1.y * iv1, p1.z * iv1, p1.w * iv1);
        }
    }

    float ivr[2][2];
    #pragma unroll
    for (int i = 0; i < 2; i++)
        #pragma unroll
        for (int hh = 0; hh < 2; hh++)
            ivr[i][hh] = invb[wm + i * 16 + g + hh * 8];

    #pragma unroll
    for (int i = 0; i < 2; i++)
        #pragma unroll
        for (int j = 0; j < 4; j++) {
            int col = wn + j * 8 + tg * 2;
            #pragma unroll
            for (int hh = 0; hh < 2; hh++) {
                int row = qt * 128 + wm + i * 16 + g + hh * 8;
                int t = b * S_ + row;
                *(float2*)&Ctx[(size_t)t * D_ + h * DEPTH_ + col] =
                    make_float2(roundtf(c[i][j][hh * 2 + 0] * ivr[i][hh]),
                                roundtf(c[i][j][hh * 2 + 1] * ivr[i][hh]));
            }
        }
}

// ---------------- fused residual + LayerNorm ----------------
template <int WRITE_ROUND>
__global__ void ln_residual(const float* __restrict__ a, const float* __restrict__ bb,
                            const float* __restrict__ g, const float* __restrict__ be,
                            float* __restrict__ out, float* __restrict__ outr) {
    const int t = blockIdx.x;
    const int tid = threadIdx.x;
    float4 va = ((const float4*)(a  + (size_t)t * D_))[tid];
    float4 vb = ((const float4*)(bb + (size_t)t * D_))[tid];
    float4 v = make_float4(va.x + vb.x, va.y + vb.y, va.z + vb.z, va.w + vb.w);

    __shared__ float sm[256];
    sm[tid] = v.x + v.y + v.z + v.w; __syncthreads();
    for (int st = 128; st > 0; st >>= 1) { if (tid < st) sm[tid] += sm[tid + st]; __syncthreads(); }
    const float mu = sm[0] * (1.0f / D_);
    __syncthreads();

    float dx = v.x - mu, dy = v.y - mu, dz = v.z - mu, dw = v.w - mu;
    sm[tid] = dx * dx + dy * dy + dz * dz + dw * dw; __syncthreads();
    for (int st = 128; st > 0; st >>= 1) { if (tid < st) sm[tid] += sm[tid + st]; __syncthreads(); }
    const float inv = rsqrtf(sm[0] * (1.0f / D_) + EPS_);

    float4 gg = ((const float4*)g)[tid];
    float4 bz = ((const float4*)be)[tid];
    float4 o = make_float4(dx * inv * gg.x + bz.x, dy * inv * gg.y + bz.y,
                           dz * inv * gg.z + bz.z, dw * inv * gg.w + bz.w);
    ((float4*)(out + (size_t)t * D_))[tid] = o;
    if (WRITE_ROUND) {
        float4 orr = make_float4(roundtf(o.x), roundtf(o.y), roundtf(o.z), roundtf(o.w));
        ((float4*)(outr + (size_t)t * D_))[tid] = orr;
    }
}

// ---------------- launch ----------------
extern "C" void kernel_launch(void* const* d_in, const int* in_sizes, int n_in,
                              void* d_out, int out_size) {
    const float* x  = (const float*)d_in[0];
    const float* Wq = (const float*)d_in[2];  const float* bq = (const float*)d_in[3];
    const float* Wk = (const float*)d_in[4];  const float* bk = (const float*)d_in[5];
    const float* Wv = (const float*)d_in[6];  const float* bv = (const float*)d_in[7];
    const float* Wo = (const float*)d_in[8];  const float* bo = (const float*)d_in[9];
    const float* W1 = (const float*)d_in[10]; const float* b1 = (const float*)d_in[11];
    const float* W2 = (const float*)d_in[12]; const float* b2 = (const float*)d_in[13];
    const float* ln1g = (const float*)d_in[14]; const float* ln1b = (const float*)d_in[15];
    const float* ln2g = (const float*)d_in[16]; const float* ln2b = (const float*)d_in[17];

    float* out  = (float*)d_out;
    float* attn = out + (size_t)NT_ * D_;

    float *qkv, *wcat, *bcat, *ctx, *ao, *x1, *x1r, *h1, *ff2, *xr, *wr, *rs, *inv;
    cudaGetSymbolAddress((void**)&qkv,  g_qkv);
    cudaGetSymbolAddress((void**)&wcat, g_wcat);
    cudaGetSymbolAddress((void**)&bcat, g_bcat);
    cudaGetSymbolAddress((void**)&ctx,  g_ctx);
    cudaGetSymbolAddress((void**)&ao,   g_ao);
    cudaGetSymbolAddress((void**)&x1,   g_x1);
    cudaGetSymbolAddress((void**)&x1r,  g_x1r);
    cudaGetSymbolAddress((void**)&h1,   g_h1);
    cudaGetSymbolAddress((void**)&ff2,  g_ff2);
    cudaGetSymbolAddress((void**)&xr,   g_xr);
    cudaGetSymbolAddress((void**)&wr,   g_wr);
    cudaGetSymbolAddress((void**)&rs,   g_rs);
    cudaGetSymbolAddress((void**)&inv,  g_inv);

    float* WqkvT = wcat;                     // [3072][1024]
    float* WoT   = wr;                       // [1024][1024]
    float* W1T   = wr + 1048576;             // [4096][1024]
    float* W2T   = wr + 5242880;             // [1024][4096]

    const int GEMM_SMEM = 3 * (ASZ_ + BSZ_) * 4;       // 61440
    const int SC_SMEM   = 2 * 128 * 68 * 4;            // 69632
    cudaFuncSetAttribute(gemm_tf32p<0,1>, cudaFuncAttributeMaxDynamicSharedMemorySize, GEMM_SMEM);
    cudaFuncSetAttribute(gemm_tf32p<0,0>, cudaFuncAttributeMaxDynamicSharedMemorySize, GEMM_SMEM);
    cudaFuncSetAttribute(gemm_tf32p<1,1>, cudaFuncAttributeMaxDynamicSharedMemorySize, GEMM_SMEM);
    cudaFuncSetAttribute(attn_scores_exp, cudaFuncAttributeMaxDynamicSharedMemorySize, SC_SMEM);

    dim3 blk(256);
    dim3 tblk(32, 8);

    // transposed + rna-rounded weights
    round_T<<<dim3(32, 32),  tblk>>>(Wq, WqkvT,           1024, 1024);
    round_T<<<dim3(32, 32),  tblk>>>(Wk, WqkvT + 1048576, 1024, 1024);
    round_T<<<dim3(32, 32),  tblk>>>(Wv, WqkvT + 2097152, 1024, 1024);
    round_T<<<dim3(32, 32),  tblk>>>(Wo, WoT,             1024, 1024);
    round_T<<<dim3(128, 32), tblk>>>(W1, W1T,             1024, 4096);
    round_T<<<dim3(32, 128), tblk>>>(W2, W2T,             4096, 1024);
    cudaMemcpyAsync(bcat,        bq, D_ * 4, cudaMemcpyDeviceToDevice);
    cudaMemcpyAsync(bcat + 1024, bk, D_ * 4, cudaMemcpyDeviceToDevice);
    cudaMemcpyAsync(bcat + 2048, bv, D_ * 4, cudaMemcpyDeviceToDevice);
    round_copy<<<4096, blk>>>(x, xr, 1048576);

    // fused QKV: [4096,1024] @ [1024,3072] (Bt = WqkvT [3072][1024])
    dim3 gQKV(LDQKV_ / 128, NT_ / 128);         // (24, 32)
    gemm_tf32p<0,1><<<gQKV, blk, GEMM_SMEM>>>(xr, WqkvT, bcat, qkv, NT_, LDQKV_, D_);

    dim3 gScore(S_ / 128, S_ / 128, B_ * H_);   // (16, 16, 32)
    attn_scores_exp<<<gScore, blk, SC_SMEM>>>(qkv, attn, rs);
    rowsum_inv<<<NROWS_ / 256, blk>>>(rs, inv);

    dim3 gPV(S_ / 128, B_ * H_);                // (16, 32)
    attn_pv_norm<<<gPV, blk>>>(attn, qkv, inv, ctx);

    dim3 gProj(D_ / 128, NT_ / 128);            // (8, 32)
    gemm_tf32p<0,0><<<gProj, blk, GEMM_SMEM>>>(ctx, WoT, bo, ao, NT_, D_, D_);
    ln_residual<1><<<NT_, blk>>>(x, ao, ln1g, ln1b, x1, x1r);

    dim3 gFF1(DFF_ / 128, NT_ / 128);           // (32, 32)
    gemm_tf32p<1,1><<<gFF1, blk, GEMM_SMEM>>>(x1r, W1T, b1, h1, NT_, DFF_, D_);
    gemm_tf32p<0,0><<<gProj, blk, GEMM_SMEM>>>(h1, W2T, b2, ff2, NT_, D_, DFF_);
    ln_residual<0><<<NT_, blk>>>(x1, ff2, ln2g, ln2b, out, nullptr);
}

// round 12
// speedup vs baseline: 1.3341x; 1.0750x over previous
#include <cuda_runtime.h>
#include <math.h>
#include <stdint.h>

#define B_ 2
#define S_ 2048
#define D_ 1024
#define H_ 16
#define DEPTH_ 64
#define DFF_ 4096
#define NT_ (B_ * S_)
#define EPS_ 1e-5f
#define LDQKV_ 3072
#define NROWS_ (B_ * H_ * S_)
#define NKT_ 16

// ---------------- scratch ----------------
__device__ float g_qkv[NT_ * LDQKV_];
__device__ float g_wcat[D_ * LDQKV_];   // WqkvT [3072][1024]
__device__ float g_bcat[LDQKV_];
__device__ float g_ctx[NT_ * D_];
__device__ float g_ao [NT_ * D_];
__device__ float g_x1 [NT_ * D_];
__device__ float g_x1r[NT_ * D_];
__device__ float g_h1 [NT_ * DFF_];
__device__ float g_ff2[NT_ * D_];
__device__ float g_xr [NT_ * D_];
__device__ float g_wr [9437184];        // WoT(1M) W1T(4M) W2T(4M)
__device__ float g_rs [NROWS_ * NKT_];
__device__ float g_inv[NROWS_];

// ---------------- helpers ----------------
__device__ __forceinline__ unsigned f2tf(float x) {
    unsigned r;
    asm("cvt.rna.tf32.f32 %0, %1;" : "=r"(r) : "f"(x));
    return r;
}
__device__ __forceinline__ float roundtf(float x) { return __uint_as_float(f2tf(x)); }

__device__ __forceinline__ void mma_tf32(float c[4],
                                         unsigned a0, unsigned a1, unsigned a2, unsigned a3,
                                         unsigned b0, unsigned b1) {
    asm volatile(
        "mma.sync.aligned.m16n8k8.row.col.f32.tf32.tf32.f32 "
        "{%0,%1,%2,%3},{%4,%5,%6,%7},{%8,%9},{%0,%1,%2,%3};\n"
        : "+f"(c[0]), "+f"(c[1]), "+f"(c[2]), "+f"(c[3])
        : "r"(a0), "r"(a1), "r"(a2), "r"(a3), "r"(b0), "r"(b1));
}

__device__ __forceinline__ void ldsm_x4(unsigned &r0, unsigned &r1, unsigned &r2, unsigned &r3,
                                        uint32_t addr) {
    asm volatile("ldmatrix.sync.aligned.m8n8.x4.shared.b16 {%0,%1,%2,%3}, [%4];"
                 : "=r"(r0), "=r"(r1), "=r"(r2), "=r"(r3) : "r"(addr));
}

__device__ __forceinline__ void cp16(void* smem, const void* gmem) {
    unsigned sa = (unsigned)__cvta_generic_to_shared(smem);
    asm volatile("cp.async.cg.shared.global [%0], [%1], 16;\n" :: "r"(sa), "l"(gmem));
}
#define CP_COMMIT() asm volatile("cp.async.commit_group;\n" ::)
#define CP_WAIT1()  asm volatile("cp.async.wait_group 1;\n" ::)
#define CP_WAIT0()  asm volatile("cp.async.wait_group 0;\n" ::)

__device__ __forceinline__ uint32_t smem_u32(const void* p) {
    return (uint32_t)__cvta_generic_to_shared(p);
}

// ---------------- pre-passes ----------------
__global__ void round_copy(const float* __restrict__ src, float* __restrict__ dst, int n4) {
    int i = blockIdx.x * 256 + threadIdx.x;
    if (i < n4) {
        float4 t = ((const float4*)src)[i];
        t.x = roundtf(t.x); t.y = roundtf(t.y); t.z = roundtf(t.z); t.w = roundtf(t.w);
        ((float4*)dst)[i] = t;
    }
}
// dst[c][r] = roundtf(src[r][c]); src R x C. block (32,8), grid (C/32, R/32)
__global__ void round_T(const float* __restrict__ src, float* __restrict__ dst, int R, int C) {
    __shared__ float t[32][33];
    int c0 = blockIdx.x * 32, r0 = blockIdx.y * 32;
    int tx = threadIdx.x, ty = threadIdx.y;
    #pragma unroll
    for (int i = 0; i < 4; i++)
        t[ty + i * 8][tx] = src[(size_t)(r0 + ty + i * 8) * C + c0 + tx];
    __syncthreads();
    #pragma unroll
    for (int i = 0; i < 4; i++)
        dst[(size_t)(c0 + ty + i * 8) * R + r0 + tx] = roundtf(t[tx][ty + i * 8]);
}

// =====================================================================
// Dense GEMM: C = A[M,K] @ Bt[N,K]^T + bias. K-tile 32, 2-stage cp.async,
// 128x128 tile, 8 warps, ldmatrix frag loads.
// Stage = 2*128*36 u32 = 36864 B; 2 stages = 73728 B -> 2 CTAs/SM.
// =====================================================================
#define ASZ_ 4608
#define BSZ_ 4608
#define LDK_ 36
template <int GELU, int ROUND>
__global__ __launch_bounds__(256, 2)
void gemm_tf32p(const float* __restrict__ A, const float* __restrict__ Bt,
                const float* __restrict__ bias, float* __restrict__ C,
                int M, int N, int K) {
    extern __shared__ unsigned dsm[];
    unsigned* Asp = dsm;                  // [2][128][36]
    unsigned* Bsp = dsm + 2 * ASZ_;       // [2][128][36]
    const uint32_t sA0 = smem_u32(Asp), sB0 = smem_u32(Bsp);

    const int tid = threadIdx.x;
    const int warp = tid >> 5, lane = tid & 31;
    const int g = lane >> 2, tg = lane & 3;
    const int m0 = blockIdx.y * 128, n0 = blockIdx.x * 128;
    const int wm = (warp >> 1) * 32, wn = (warp & 1) * 64;

    // ldmatrix address components
    const int a_row = wm + (lane & 15);
    const int a_col = (lane >> 4) * 4;
    const int b_row = (lane & 7) + ((lane >> 4) & 1) * 8;
    const int b_col = ((lane >> 3) & 1) * 4;

    // loader: thread t does rows rL + 32i, 16B chunk kcL
    const int rL = tid >> 3, kcL = (tid & 7) * 4;

    float c[2][8][4] = {};
    const int T = K >> 5;

    // prologue: stage 0
    #pragma unroll
    for (int i = 0; i < 4; i++) {
        cp16(&Asp[(rL + i * 32) * LDK_ + kcL], &A[(size_t)(m0 + rL + i * 32) * K + kcL]);
        cp16(&Bsp[(rL + i * 32) * LDK_ + kcL], &Bt[(size_t)(n0 + rL + i * 32) * K + kcL]);
    }
    CP_COMMIT();

    for (int t = 0; t < T; t++) {
        if (t + 1 < T) {
            const int s = (t + 1) & 1, k0 = (t + 1) << 5;
            #pragma unroll
            for (int i = 0; i < 4; i++) {
                cp16(&Asp[s * ASZ_ + (rL + i * 32) * LDK_ + kcL],
                     &A[(size_t)(m0 + rL + i * 32) * K + k0 + kcL]);
                cp16(&Bsp[s * BSZ_ + (rL + i * 32) * LDK_ + kcL],
                     &Bt[(size_t)(n0 + rL + i * 32) * K + k0 + kcL]);
            }
            CP_COMMIT();
            CP_WAIT1();
        } else {
            CP_WAIT0();
        }
        __syncthreads();
        const uint32_t sA = sA0 + (t & 1) * ASZ_ * 4;
        const uint32_t sB = sB0 + (t & 1) * BSZ_ * 4;
        #pragma unroll
        for (int ks = 0; ks < 32; ks += 8) {
            unsigned a[2][4], b[8][2];
            #pragma unroll
            for (int i = 0; i < 2; i++)
                ldsm_x4(a[i][0], a[i][1], a[i][2], a[i][3],
                        sA + (uint32_t)(((a_row + i * 16) * LDK_ + ks + a_col) * 4));
            #pragma unroll
            for (int jj = 0; jj < 4; jj++)
                ldsm_x4(b[2 * jj][0], b[2 * jj][1], b[2 * jj + 1][0], b[2 * jj + 1][1],
                        sB + (uint32_t)(((wn + jj * 16 + b_row) * LDK_ + ks + b_col) * 4));
            #pragma unroll
            for (int i = 0; i < 2; i++)
                #pragma unroll
                for (int j = 0; j < 8; j++)
                    mma_tf32(c[i][j], a[i][0], a[i][1], a[i][2], a[i][3], b[j][0], b[j][1]);
        }
        __syncthreads();
    }

    #pragma unroll
    for (int i = 0; i < 2; i++) {
        #pragma unroll
        for (int j = 0; j < 8; j++) {
            int col = n0 + wn + j * 8 + tg * 2;
            float b0v = bias[col], b1v = bias[col + 1];
            #pragma unroll
            for (int h = 0; h < 2; h++) {
                int row = m0 + wm + i * 16 + g + h * 8;
                float v0 = c[i][j][h * 2 + 0] + b0v;
                float v1 = c[i][j][h * 2 + 1] + b1v;
                if (GELU) {
                    v0 = 0.5f * v0 * (1.0f + erff(v0 * 0.70710678118654752f));
                    v1 = 0.5f * v1 * (1.0f + erff(v1 * 0.70710678118654752f));
                }
                if (ROUND) { v0 = roundtf(v0); v1 = roundtf(v1); }
                *(float2*)&C[(size_t)row * N + col] = make_float2(v0, v1);
            }
        }
    }
}

// =====================================================================
// Scores + exp + partial row sums; kt>qt blocks zero-fill.
// ldmatrix fragment loads for Q and K (both K-major rows, stride 68).
// =====================================================================
__global__ __launch_bounds__(256, 2)
void attn_scores_exp(const float* __restrict__ QKV, float* __restrict__ attnP,
                     float* __restrict__ rs) {
    const int kt = blockIdx.x, qt = blockIdx.y, bh = blockIdx.z;
    const int tid = threadIdx.x;

    if (kt > qt) {
        float4 z = make_float4(0.f, 0.f, 0.f, 0.f);
        float* tb = attnP + ((size_t)bh * S_ + qt * 128) * S_ + kt * 128;
        #pragma unroll
        for (int e = 0; e < 16; e++) {
            int u = tid + e * 256;
            int r = u >> 5, c4 = u & 31;
            ((float4*)(tb + (size_t)r * S_))[c4] = z;
        }
        return;
    }

    const int b = bh >> 4, h = bh & 15;

    extern __shared__ unsigned dsm[];
    unsigned* Qs = dsm;              // [128][68]
    unsigned* Ks = dsm + 128 * 68;
    const uint32_t sQ = smem_u32(Qs), sK = smem_u32(Ks);

    const int warp = tid >> 5, lane = tid & 31;
    const int g = lane >> 2, tg = lane & 3;
    const int wm = (warp >> 1) * 32, wn = (warp & 1) * 64;

    const int a_row = wm + (lane & 15);
    const int a_col = (lane >> 4) * 4;
    const int b_row = (lane & 7) + ((lane >> 4) & 1) * 8;
    const int b_col = ((lane >> 3) & 1) * 4;

    const float* qb = QKV + (size_t)(b * S_ + qt * 128) * LDQKV_ + h * DEPTH_;
    const float* kb = QKV + (size_t)(b * S_ + kt * 128) * LDQKV_ + 1024 + h * DEPTH_;

    #pragma unroll
    for (int e = 0; e < 8; e++) {
        int u = tid + e * 256;
        int r = u >> 4, cc = (u & 15) * 4;
        cp16(&Qs[r * 68 + cc], &qb[(size_t)r * LDQKV_ + cc]);
        cp16(&Ks[r * 68 + cc], &kb[(size_t)r * LDQKV_ + cc]);
    }
    CP_COMMIT();
    CP_WAIT0();
    __syncthreads();

    float c[2][8][4] = {};
    #pragma unroll
    for (int ks = 0; ks < 64; ks += 8) {
        unsigned a[2][4], bfr[8][2];
        #pragma unroll
        for (int i = 0; i < 2; i++)
            ldsm_x4(a[i][0], a[i][1], a[i][2], a[i][3],
                    sQ + (uint32_t)(((a_row + i * 16) * 68 + ks + a_col) * 4));
        #pragma unroll
        for (int jj = 0; jj < 4; jj++)
            ldsm_x4(bfr[2 * jj][0], bfr[2 * jj][1], bfr[2 * jj + 1][0], bfr[2 * jj + 1][1],
                    sK + (uint32_t)(((wn + jj * 16 + b_row) * 68 + ks + b_col) * 4));
        #pragma unroll
        for (int i = 0; i < 2; i++)
            #pragma unroll
            for (int j = 0; j < 8; j++)
                mma_tf32(c[i][j], a[i][0], a[i][1], a[i][2], a[i][3], bfr[j][0], bfr[j][1]);
    }

    const bool diag = (kt == qt);
    float rsum[2][2] = {};
    float* ob = attnP + ((size_t)bh * S_ + qt * 128) * S_ + kt * 128;
    #pragma unroll
    for (int i = 0; i < 2; i++)
        #pragma unroll
        for (int j = 0; j < 8; j++) {
            int col = wn + j * 8 + tg * 2;
            #pragma unroll
            for (int hh = 0; hh < 2; hh++) {
                int row = wm + i * 16 + g + hh * 8;
                float v0 = __expf(c[i][j][hh * 2 + 0] * 0.03125f);
                float v1 = __expf(c[i][j][hh * 2 + 1] * 0.03125f);
                if (diag) {
                    if (col     > row) v0 = 0.f;
                    if (col + 1 > row) v1 = 0.f;
                }
                rsum[i][hh] += v0 + v1;
                *(float2*)&ob[(size_t)row * S_ + col] = make_float2(v0, v1);
            }
        }

    #pragma unroll
    for (int i = 0; i < 2; i++)
        #pragma unroll
        for (int hh = 0; hh < 2; hh++) {
            rsum[i][hh] += __shfl_xor_sync(0xffffffff, rsum[i][hh], 1);
            rsum[i][hh] += __shfl_xor_sync(0xffffffff, rsum[i][hh], 2);
        }
    __syncthreads();
    float* psm = (float*)Qs;
    if (tg == 0) {
        #pragma unroll
        for (int i = 0; i < 2; i++)
            #pragma unroll
            for (int hh = 0; hh < 2; hh++)
                psm[(wm + i * 16 + g + hh * 8) * 2 + (wn >> 6)] = rsum[i][hh];
    }
    __syncthreads();
    if (tid < 128)
        rs[((size_t)bh * S_ + qt * 128 + tid) * NKT_ + kt] = psm[tid * 2] + psm[tid * 2 + 1];
}

// ---------------- inv[row] = 1 / sum of valid partials ----------------
__global__ void rowsum_inv(const float* __restrict__ rs, float* __restrict__ inv) {
    int row = blockIdx.x * 256 + threadIdx.x;
    int qt = (row & (S_ - 1)) >> 7;
    float s = 0.f;
    for (int kt = 0; kt <= qt; kt++) s += rs[(size_t)row * NKT_ + kt];
    inv[row] = 1.0f / s;
}

// =====================================================================
// ctx = (P' @ V) * inv; normalized attn written back FROM SMEM in-loop.
// Longest-first qt; A-frags via ldmatrix, V-frags via LDS.
// =====================================================================
__global__ __launch_bounds__(256, 2)
void attn_pv_norm(float* __restrict__ attnP, const float* __restrict__ QKV,
                  const float* __restrict__ inv, float* __restrict__ Ctx) {
    const int qt = NKT_ - 1 - blockIdx.x, bh = blockIdx.y;
    const int b = bh >> 4, h = bh & 15;

    __shared__ unsigned As[2][128][20];
    __shared__ unsigned Bs[2][16][72];
    const uint32_t sAbase = smem_u32(&As[0][0][0]);

    const int tid = threadIdx.x;
    const int warp = tid >> 5, lane = tid & 31;
    const int g = lane >> 2, tg = lane & 3;
    const int wm = (warp >> 1) * 32, wn = (warp & 1) * 32;

    const int a_row = wm + (lane & 15);
    const int a_col = (lane >> 4) * 4;

    float* Ab = attnP + ((size_t)bh * S_ + qt * 128) * S_;
    const float* Vb = QKV + (size_t)(b * S_) * LDQKV_ + 2048 + h * DEPTH_;
    const float* invb = inv + (size_t)bh * S_ + qt * 128;

    const int rA = tid >> 2, kqA = (tid & 3) * 4;
    const int kB = tid >> 4, nqB = (tid & 15) * 4;

    const float iv0 = invb[rA], iv1 = invb[rA + 64];

    float c[2][4][4] = {};
    const int T = (qt + 1) * 8;

    #pragma unroll
    for (int i = 0; i < 2; i++)
        cp16(&As[0][rA + i * 64][kqA], &Ab[(size_t)(rA + i * 64) * S_ + kqA]);
    cp16(&Bs[0][kB][nqB], &Vb[(size_t)kB * LDQKV_ + nqB]);
    CP_COMMIT();

    for (int t = 0; t < T; t++) {
        if (t + 1 < T) {
            const int k0 = (t + 1) << 4, st = (t + 1) & 1;
            #pragma unroll
            for (int i = 0; i < 2; i++)
                cp16(&As[st][rA + i * 64][kqA], &Ab[(size_t)(rA + i * 64) * S_ + k0 + kqA]);
            cp16(&Bs[st][kB][nqB], &Vb[(size_t)(k0 + kB) * LDQKV_ + nqB]);
            CP_COMMIT();
            CP_WAIT1();
        } else {
            CP_WAIT0();
        }
        __syncthreads();
        const int st = t & 1;
        const uint32_t sA = sAbase + (uint32_t)(st * 128 * 20 * 4);
        #pragma unroll
        for (int ks = 0; ks < 16; ks += 8) {
            unsigned a[2][4], bfr[4][2];
            #pragma unroll
            for (int i = 0; i < 2; i++)
                ldsm_x4(a[i][0], a[i][1], a[i][2], a[i][3],
                        sA + (uint32_t)(((a_row + i * 16) * 20 + ks + a_col) * 4));
            #pragma unroll
            for (int j = 0; j < 4; j++) {
                int nB = wn + j * 8;
                bfr[j][0] = Bs[st][ks + tg    ][nB + g];
                bfr[j][1] = Bs[st][ks + tg + 4][nB + g];
            }
            #pragma unroll
            for (int i = 0; i < 2; i++)
                #pragma unroll
                for (int j = 0; j < 4; j++)
                    mma_tf32(c[i][j], a[i][0], a[i][1], a[i][2], a[i][3], bfr[j][0], bfr[j][1]);
        }
        // normalized write-back of this stage's P tile from smem
        {
            float4 p0 = *(float4*)&As[st][rA][kqA];
            float4 p1 = *(float4*)&As[st][rA + 64][kqA];
            *(float4*)&Ab[(size_t)rA * S_ + t * 16 + kqA] =
                make_float4(p0.x * iv0, p0.y * iv0, p0.z * iv0, p0.w * iv0);
            *(float4*)&Ab[(size_t)(rA + 64) * S_ + t * 16 + kqA] =
                make_float4(p1.x * iv1, p1.y * iv1, p1.z * iv1, p1.w * iv1);
        }
    }

    float ivr[2][2];
    #pragma unroll
    for (int i = 0; i < 2; i++)
        #pragma unroll
        for (int hh = 0; hh < 2; hh++)
            ivr[i][hh] = invb[wm + i * 16 + g + hh * 8];

    #pragma unroll
    for (int i = 0; i < 2; i++)
        #pragma unroll
        for (int j = 0; j < 4; j++) {
            int col = wn + j * 8 + tg * 2;
            #pragma unroll
            for (int hh = 0; hh < 2; hh++) {
                int row = qt * 128 + wm + i * 16 + g + hh * 8;
                int t = b * S_ + row;
                *(float2*)&Ctx[(size_t)t * D_ + h * DEPTH_ + col] =
                    make_float2(roundtf(c[i][j][hh * 2 + 0] * ivr[i][hh]),
                                roundtf(c[i][j][hh * 2 + 1] * ivr[i][hh]));
            }
        }
}

// ---------------- fused residual + LayerNorm ----------------
template <int WRITE_ROUND>
__global__ void ln_residual(const float* __restrict__ a, const float* __restrict__ bb,
                            const float* __restrict__ g, const float* __restrict__ be,
                            float* __restrict__ out, float* __restrict__ outr) {
    const int t = blockIdx.x;
    const int tid = threadIdx.x;
    float4 va = ((const float4*)(a  + (size_t)t * D_))[tid];
    float4 vb = ((const float4*)(bb + (size_t)t * D_))[tid];
    float4 v = make_float4(va.x + vb.x, va.y + vb.y, va.z + vb.z, va.w + vb.w);

    __shared__ float sm[256];
    sm[tid] = v.x + v.y + v.z + v.w; __syncthreads();
    for (int st = 128; st > 0; st >>= 1) { if (tid < st) sm[tid] += sm[tid + st]; __syncthreads(); }
    const float mu = sm[0] * (1.0f / D_);
    __syncthreads();

    float dx = v.x - mu, dy = v.y - mu, dz = v.z - mu, dw = v.w - mu;
    sm[tid] = dx * dx + dy * dy + dz * dz + dw * dw; __syncthreads();
    for (int st = 128; st > 0; st >>= 1) { if (tid < st) sm[tid] += sm[tid + st]; __syncthreads(); }
    const float inv = rsqrtf(sm[0] * (1.0f / D_) + EPS_);

    float4 gg = ((const float4*)g)[tid];
    float4 bz = ((const float4*)be)[tid];
    float4 o = make_float4(dx * inv * gg.x + bz.x, dy * inv * gg.y + bz.y,
                           dz * inv * gg.z + bz.z, dw * inv * gg.w + bz.w);
    ((float4*)(out + (size_t)t * D_))[tid] = o;
    if (WRITE_ROUND) {
        float4 orr = make_float4(roundtf(o.x), roundtf(o.y), roundtf(o.z), roundtf(o.w));
        ((float4*)(outr + (size_t)t * D_))[tid] = orr;
    }
}

// ---------------- launch ----------------
extern "C" void kernel_launch(void* const* d_in, const int* in_sizes, int n_in,
                              void* d_out, int out_size) {
    const float* x  = (const float*)d_in[0];
    const float* Wq = (const float*)d_in[2];  const float* bq = (const float*)d_in[3];
    const float* Wk = (const float*)d_in[4];  const float* bk = (const float*)d_in[5];
    const float* Wv = (const float*)d_in[6];  const float* bv = (const float*)d_in[7];
    const float* Wo = (const float*)d_in[8];  const float* bo = (const float*)d_in[9];
    const float* W1 = (const float*)d_in[10]; const float* b1 = (const float*)d_in[11];
    const float* W2 = (const float*)d_in[12]; const float* b2 = (const float*)d_in[13];
    const float* ln1g = (const float*)d_in[14]; const float* ln1b = (const float*)d_in[15];
    const float* ln2g = (const float*)d_in[16]; const float* ln2b = (const float*)d_in[17];

    float* out  = (float*)d_out;
    float* attn = out + (size_t)NT_ * D_;

    float *qkv, *wcat, *bcat, *ctx, *ao, *x1, *x1r, *h1, *ff2, *xr, *wr, *rs, *inv;
    cudaGetSymbolAddress((void**)&qkv,  g_qkv);
    cudaGetSymbolAddress((void**)&wcat, g_wcat);
    cudaGetSymbolAddress((void**)&bcat, g_bcat);
    cudaGetSymbolAddress((void**)&ctx,  g_ctx);
    cudaGetSymbolAddress((void**)&ao,   g_ao);
    cudaGetSymbolAddress((void**)&x1,   g_x1);
    cudaGetSymbolAddress((void**)&x1r,  g_x1r);
    cudaGetSymbolAddress((void**)&h1,   g_h1);
    cudaGetSymbolAddress((void**)&ff2,  g_ff2);
    cudaGetSymbolAddress((void**)&xr,   g_xr);
    cudaGetSymbolAddress((void**)&wr,   g_wr);
    cudaGetSymbolAddress((void**)&rs,   g_rs);
    cudaGetSymbolAddress((void**)&inv,  g_inv);

    float* WqkvT = wcat;                     // [3072][1024]
    float* WoT   = wr;                       // [1024][1024]
    float* W1T   = wr + 1048576;             // [4096][1024]
    float* W2T   = wr + 5242880;             // [1024][4096]

    const int GEMM_SMEM = 2 * (ASZ_ + BSZ_) * 4;       // 73728
    const int SC_SMEM   = 2 * 128 * 68 * 4;            // 69632
    cudaFuncSetAttribute(gemm_tf32p<0,1>, cudaFuncAttributeMaxDynamicSharedMemorySize, GEMM_SMEM);
    cudaFuncSetAttribute(gemm_tf32p<0,0>, cudaFuncAttributeMaxDynamicSharedMemorySize, GEMM_SMEM);
    cudaFuncSetAttribute(gemm_tf32p<1,1>, cudaFuncAttributeMaxDynamicSharedMemorySize, GEMM_SMEM);
    cudaFuncSetAttribute(attn_scores_exp, cudaFuncAttributeMaxDynamicSharedMemorySize, SC_SMEM);

    dim3 blk(256);
    dim3 tblk(32, 8);

    // transposed + rna-rounded weights
    round_T<<<dim3(32, 32),  tblk>>>(Wq, WqkvT,           1024, 1024);
    round_T<<<dim3(32, 32),  tblk>>>(Wk, WqkvT + 1048576, 1024, 1024);
    round_T<<<dim3(32, 32),  tblk>>>(Wv, WqkvT + 2097152, 1024, 1024);
    round_T<<<dim3(32, 32),  tblk>>>(Wo, WoT,             1024, 1024);
    round_T<<<dim3(128, 32), tblk>>>(W1, W1T,             1024, 4096);
    round_T<<<dim3(32, 128), tblk>>>(W2, W2T,             4096, 1024);
    cudaMemcpyAsync(bcat,        bq, D_ * 4, cudaMemcpyDeviceToDevice);
    cudaMemcpyAsync(bcat + 1024, bk, D_ * 4, cudaMemcpyDeviceToDevice);
    cudaMemcpyAsync(bcat + 2048, bv, D_ * 4, cudaMemcpyDeviceToDevice);
    round_copy<<<4096, blk>>>(x, xr, 1048576);

    // fused QKV: [4096,1024] @ [1024,3072] (Bt = WqkvT [3072][1024])
    dim3 gQKV(LDQKV_ / 128, NT_ / 128);         // (24, 32)
    gemm_tf32p<0,1><<<gQKV, blk, GEMM_SMEM>>>(xr, WqkvT, bcat, qkv, NT_, LDQKV_, D_);

    dim3 gScore(S_ / 128, S_ / 128, B_ * H_);   // (16, 16, 32)
    attn_scores_exp<<<gScore, blk, SC_SMEM>>>(qkv, attn, rs);
    rowsum_inv<<<NROWS_ / 256, blk>>>(rs, inv);

    dim3 gPV(S_ / 128, B_ * H_);                // (16, 32)
    attn_pv_norm<<<gPV, blk>>>(attn, qkv, inv, ctx);

    dim3 gProj(D_ / 128, NT_ / 128);            // (8, 32)
    gemm_tf32p<0,0><<<gProj, blk, GEMM_SMEM>>>(ctx, WoT, bo, ao, NT_, D_, D_);
    ln_residual<1><<<NT_, blk>>>(x, ao, ln1g, ln1b, x1, x1r);

    dim3 gFF1(DFF_ / 128, NT_ / 128);           // (32, 32)
    gemm_tf32p<1,1><<<gFF1, blk, GEMM_SMEM>>>(x1r, W1T, b1, h1, NT_, DFF_, D_);
    gemm_tf32p<0,0><<<gProj, blk, GEMM_SMEM>>>(h1, W2T, b2, ff2, NT_, D_, DFF_);
    ln_residual<0><<<NT_, blk>>>(x1, ff2, ln2g, ln2b, out, nullptr);
}

// round 13
// speedup vs baseline: 1.3963x; 1.0466x over previous
#include <cuda_runtime.h>
#include <math.h>
#include <stdint.h>

#define B_ 2
#define S_ 2048
#define D_ 1024
#define H_ 16
#define DEPTH_ 64
#define DFF_ 4096
#define NT_ (B_ * S_)
#define EPS_ 1e-5f
#define LDQKV_ 3072
#define NROWS_ (B_ * H_ * S_)
#define NKT_ 16

// ---------------- scratch ----------------
__device__ float g_qkv[NT_ * LDQKV_];
__device__ float g_wcat[D_ * LDQKV_];   // WqkvT [3072][1024]
__device__ float g_bcat[LDQKV_];
__device__ float g_ctx[NT_ * D_];
__device__ float g_ao [NT_ * D_];
__device__ float g_x1 [NT_ * D_];
__device__ float g_x1r[NT_ * D_];
__device__ float g_h1 [NT_ * DFF_];
__device__ float g_ff2[NT_ * D_];
__device__ float g_xr [NT_ * D_];
__device__ float g_wr [9437184];        // WoT(1M) W1T(4M) W2T(4M)
__device__ float g_rs [NROWS_ * NKT_];
__device__ float g_inv[NROWS_];

// ---------------- helpers ----------------
__device__ __forceinline__ unsigned f2tf(float x) {
    unsigned r;
    asm("cvt.rna.tf32.f32 %0, %1;" : "=r"(r) : "f"(x));
    return r;
}
__device__ __forceinline__ float roundtf(float x) { return __uint_as_float(f2tf(x)); }

__device__ __forceinline__ void mma_tf32(float c[4],
                                         unsigned a0, unsigned a1, unsigned a2, unsigned a3,
                                         unsigned b0, unsigned b1) {
    asm volatile(
        "mma.sync.aligned.m16n8k8.row.col.f32.tf32.tf32.f32 "
        "{%0,%1,%2,%3},{%4,%5,%6,%7},{%8,%9},{%0,%1,%2,%3};\n"
        : "+f"(c[0]), "+f"(c[1]), "+f"(c[2]), "+f"(c[3])
        : "r"(a0), "r"(a1), "r"(a2), "r"(a3), "r"(b0), "r"(b1));
}

__device__ __forceinline__ void ldsm_x4(unsigned &r0, unsigned &r1, unsigned &r2, unsigned &r3,
                                        uint32_t addr) {
    asm volatile("ldmatrix.sync.aligned.m8n8.x4.shared.b16 {%0,%1,%2,%3}, [%4];"
                 : "=r"(r0), "=r"(r1), "=r"(r2), "=r"(r3) : "r"(addr));
}

__device__ __forceinline__ void cp16(void* smem, const void* gmem) {
    unsigned sa = (unsigned)__cvta_generic_to_shared(smem);
    asm volatile("cp.async.cg.shared.global [%0], [%1], 16;\n" :: "r"(sa), "l"(gmem));
}
#define CP_COMMIT() asm volatile("cp.async.commit_group;\n" ::)
#define CP_WAIT1()  asm volatile("cp.async.wait_group 1;\n" ::)
#define CP_WAIT0()  asm volatile("cp.async.wait_group 0;\n" ::)

__device__ __forceinline__ uint32_t smem_u32(const void* p) {
    return (uint32_t)__cvta_generic_to_shared(p);
}

// ---------------- pre-passes ----------------
__global__ void round_copy(const float* __restrict__ src, float* __restrict__ dst, int n4) {
    int i = blockIdx.x * 256 + threadIdx.x;
    if (i < n4) {
        float4 t = ((const float4*)src)[i];
        t.x = roundtf(t.x); t.y = roundtf(t.y); t.z = roundtf(t.z); t.w = roundtf(t.w);
        ((float4*)dst)[i] = t;
    }
}
// dst[c][r] = roundtf(src[r][c]); src R x C. block (32,8), grid (C/32, R/32)
__global__ void round_T(const float* __restrict__ src, float* __restrict__ dst, int R, int C) {
    __shared__ float t[32][33];
    int c0 = blockIdx.x * 32, r0 = blockIdx.y * 32;
    int tx = threadIdx.x, ty = threadIdx.y;
    #pragma unroll
    for (int i = 0; i < 4; i++)
        t[ty + i * 8][tx] = src[(size_t)(r0 + ty + i * 8) * C + c0 + tx];
    __syncthreads();
    #pragma unroll
    for (int i = 0; i < 4; i++)
        dst[(size_t)(c0 + ty + i * 8) * R + r0 + tx] = roundtf(t[tx][ty + i * 8]);
}

// =====================================================================
// Dense GEMM: C = A[M,K] @ Bt[N,K]^T + bias. K-tile 32, 2-stage cp.async,
// 128x128 tile, 8 warps, ldmatrix frag loads. (verified R12)
// =====================================================================
#define ASZ_ 4608
#define BSZ_ 4608
#define LDK_ 36
template <int GELU, int ROUND>
__global__ __launch_bounds__(256, 2)
void gemm_tf32p(const float* __restrict__ A, const float* __restrict__ Bt,
                const float* __restrict__ bias, float* __restrict__ C,
                int M, int N, int K) {
    extern __shared__ unsigned dsm[];
    unsigned* Asp = dsm;                  // [2][128][36]
    unsigned* Bsp = dsm + 2 * ASZ_;       // [2][128][36]
    const uint32_t sA0 = smem_u32(Asp), sB0 = smem_u32(Bsp);

    const int tid = threadIdx.x;
    const int warp = tid >> 5, lane = tid & 31;
    const int g = lane >> 2, tg = lane & 3;
    const int m0 = blockIdx.y * 128, n0 = blockIdx.x * 128;
    const int wm = (warp >> 1) * 32, wn = (warp & 1) * 64;

    const int a_row = wm + (lane & 15);
    const int a_col = (lane >> 4) * 4;
    const int b_row = (lane & 7) + ((lane >> 4) & 1) * 8;
    const int b_col = ((lane >> 3) & 1) * 4;

    const int rL = tid >> 3, kcL = (tid & 7) * 4;

    float c[2][8][4] = {};
    const int T = K >> 5;

    #pragma unroll
    for (int i = 0; i < 4; i++) {
        cp16(&Asp[(rL + i * 32) * LDK_ + kcL], &A[(size_t)(m0 + rL + i * 32) * K + kcL]);
        cp16(&Bsp[(rL + i * 32) * LDK_ + kcL], &Bt[(size_t)(n0 + rL + i * 32) * K + kcL]);
    }
    CP_COMMIT();

    for (int t = 0; t < T; t++) {
        if (t + 1 < T) {
            const int s = (t + 1) & 1, k0 = (t + 1) << 5;
            #pragma unroll
            for (int i = 0; i < 4; i++) {
                cp16(&Asp[s * ASZ_ + (rL + i * 32) * LDK_ + kcL],
                     &A[(size_t)(m0 + rL + i * 32) * K + k0 + kcL]);
                cp16(&Bsp[s * BSZ_ + (rL + i * 32) * LDK_ + kcL],
                     &Bt[(size_t)(n0 + rL + i * 32) * K + k0 + kcL]);
            }
            CP_COMMIT();
            CP_WAIT1();
        } else {
            CP_WAIT0();
        }
        __syncthreads();
        const uint32_t sA = sA0 + (t & 1) * ASZ_ * 4;
        const uint32_t sB = sB0 + (t & 1) * BSZ_ * 4;
        #pragma unroll
        for (int ks = 0; ks < 32; ks += 8) {
            unsigned a[2][4], b[8][2];
            #pragma unroll
            for (int i = 0; i < 2; i++)
                ldsm_x4(a[i][0], a[i][1], a[i][2], a[i][3],
                        sA + (uint32_t)(((a_row + i * 16) * LDK_ + ks + a_col) * 4));
            #pragma unroll
            for (int jj = 0; jj < 4; jj++)
                ldsm_x4(b[2 * jj][0], b[2 * jj][1], b[2 * jj + 1][0], b[2 * jj + 1][1],
                        sB + (uint32_t)(((wn + jj * 16 + b_row) * LDK_ + ks + b_col) * 4));
            #pragma unroll
            for (int i = 0; i < 2; i++)
                #pragma unroll
                for (int j = 0; j < 8; j++)
                    mma_tf32(c[i][j], a[i][0], a[i][1], a[i][2], a[i][3], b[j][0], b[j][1]);
        }
        __syncthreads();
    }

    #pragma unroll
    for (int i = 0; i < 2; i++) {
        #pragma unroll
        for (int j = 0; j < 8; j++) {
            int col = n0 + wn + j * 8 + tg * 2;
            float b0v = bias[col], b1v = bias[col + 1];
            #pragma unroll
            for (int h = 0; h < 2; h++) {
                int row = m0 + wm + i * 16 + g + h * 8;
                float v0 = c[i][j][h * 2 + 0] + b0v;
                float v1 = c[i][j][h * 2 + 1] + b1v;
                if (GELU) {
                    v0 = 0.5f * v0 * (1.0f + erff(v0 * 0.70710678118654752f));
                    v1 = 0.5f * v1 * (1.0f + erff(v1 * 0.70710678118654752f));
                }
                if (ROUND) { v0 = roundtf(v0); v1 = roundtf(v1); }
                *(float2*)&C[(size_t)row * N + col] = make_float2(v0, v1);
            }
        }
    }
}

// =====================================================================
// Scores + exp + partial row sums; kt>qt blocks zero-fill. (verified R10/12)
// =====================================================================
__global__ __launch_bounds__(256, 2)
void attn_scores_exp(const float* __restrict__ QKV, float* __restrict__ attnP,
                     float* __restrict__ rs) {
    const int kt = blockIdx.x, qt = blockIdx.y, bh = blockIdx.z;
    const int tid = threadIdx.x;

    if (kt > qt) {
        float4 z = make_float4(0.f, 0.f, 0.f, 0.f);
        float* tb = attnP + ((size_t)bh * S_ + qt * 128) * S_ + kt * 128;
        #pragma unroll
        for (int e = 0; e < 16; e++) {
            int u = tid + e * 256;
            int r = u >> 5, c4 = u & 31;
            ((float4*)(tb + (size_t)r * S_))[c4] = z;
        }
        return;
    }

    const int b = bh >> 4, h = bh & 15;

    extern __shared__ unsigned dsm[];
    unsigned* Qs = dsm;              // [128][68]
    unsigned* Ks = dsm + 128 * 68;
    const uint32_t sQ = smem_u32(Qs), sK = smem_u32(Ks);

    const int warp = tid >> 5, lane = tid & 31;
    const int g = lane >> 2, tg = lane & 3;
    const int wm = (warp >> 1) * 32, wn = (warp & 1) * 64;

    const int a_row = wm + (lane & 15);
    const int a_col = (lane >> 4) * 4;
    const int b_row = (lane & 7) + ((lane >> 4) & 1) * 8;
    const int b_col = ((lane >> 3) & 1) * 4;

    const float* qb = QKV + (size_t)(b * S_ + qt * 128) * LDQKV_ + h * DEPTH_;
    const float* kb = QKV + (size_t)(b * S_ + kt * 128) * LDQKV_ + 1024 + h * DEPTH_;

    #pragma unroll
    for (int e = 0; e < 8; e++) {
        int u = tid + e * 256;
        int r = u >> 4, cc = (u & 15) * 4;
        cp16(&Qs[r * 68 + cc], &qb[(size_t)r * LDQKV_ + cc]);
        cp16(&Ks[r * 68 + cc], &kb[(size_t)r * LDQKV_ + cc]);
    }
    CP_COMMIT();
    CP_WAIT0();
    __syncthreads();

    float c[2][8][4] = {};
    #pragma unroll
    for (int ks = 0; ks < 64; ks += 8) {
        unsigned a[2][4], bfr[8][2];
        #pragma unroll
        for (int i = 0; i < 2; i++)
            ldsm_x4(a[i][0], a[i][1], a[i][2], a[i][3],
                    sQ + (uint32_t)(((a_row + i * 16) * 68 + ks + a_col) * 4));
        #pragma unroll
        for (int jj = 0; jj < 4; jj++)
            ldsm_x4(bfr[2 * jj][0], bfr[2 * jj][1], bfr[2 * jj + 1][0], bfr[2 * jj + 1][1],
                    sK + (uint32_t)(((wn + jj * 16 + b_row) * 68 + ks + b_col) * 4));
        #pragma unroll
        for (int i = 0; i < 2; i++)
            #pragma unroll
            for (int j = 0; j < 8; j++)
                mma_tf32(c[i][j], a[i][0], a[i][1], a[i][2], a[i][3], bfr[j][0], bfr[j][1]);
    }

    const bool diag = (kt == qt);
    float rsum[2][2] = {};
    float* ob = attnP + ((size_t)bh * S_ + qt * 128) * S_ + kt * 128;
    #pragma unroll
    for (int i = 0; i < 2; i++)
        #pragma unroll
        for (int j = 0; j < 8; j++) {
            int col = wn + j * 8 + tg * 2;
            #pragma unroll
            for (int hh = 0; hh < 2; hh++) {
                int row = wm + i * 16 + g + hh * 8;
                float v0 = __expf(c[i][j][hh * 2 + 0] * 0.03125f);
                float v1 = __expf(c[i][j][hh * 2 + 1] * 0.03125f);
                if (diag) {
                    if (col     > row) v0 = 0.f;
                    if (col + 1 > row) v1 = 0.f;
                }
                rsum[i][hh] += v0 + v1;
                *(float2*)&ob[(size_t)row * S_ + col] = make_float2(v0, v1);
            }
        }

    #pragma unroll
    for (int i = 0; i < 2; i++)
        #pragma unroll
        for (int hh = 0; hh < 2; hh++) {
            rsum[i][hh] += __shfl_xor_sync(0xffffffff, rsum[i][hh], 1);
            rsum[i][hh] += __shfl_xor_sync(0xffffffff, rsum[i][hh], 2);
        }
    __syncthreads();
    float* psm = (float*)Qs;
    if (tg == 0) {
        #pragma unroll
        for (int i = 0; i < 2; i++)
            #pragma unroll
            for (int hh = 0; hh < 2; hh++)
                psm[(wm + i * 16 + g + hh * 8) * 2 + (wn >> 6)] = rsum[i][hh];
    }
    __syncthreads();
    if (tid < 128)
        rs[((size_t)bh * S_ + qt * 128 + tid) * NKT_ + kt] = psm[tid * 2] + psm[tid * 2 + 1];
}

// ---------------- inv[row] = 1 / sum of valid partials ----------------
__global__ void rowsum_inv(const float* __restrict__ rs, float* __restrict__ inv) {
    int row = blockIdx.x * 256 + threadIdx.x;
    int qt = (row & (S_ - 1)) >> 7;
    float s = 0.f;
    for (int kt = 0; kt <= qt; kt++) s += rs[(size_t)row * NKT_ + kt];
    inv[row] = 1.0f / s;
}

// =====================================================================
// ctx = (P' @ V) * inv; K-tile 32 (barriers halved); normalized attn
// written back FROM SMEM in-loop. Longest-first qt.
// As [2][128][36], Bs [2][32][72] = 55296 B static -> 2 CTAs/SM.
// =====================================================================
__global__ __launch_bounds__(256, 2)
void attn_pv_norm(float* __restrict__ attnP, const float* __restrict__ QKV,
                  const float* __restrict__ inv, float* __restrict__ Ctx) {
    const int qt = NKT_ - 1 - blockIdx.x, bh = blockIdx.y;
    const int b = bh >> 4, h = bh & 15;

    __shared__ unsigned As[2][128][36];
    __shared__ unsigned Bs[2][32][72];
    const uint32_t sAbase = smem_u32(&As[0][0][0]);

    const int tid = threadIdx.x;
    const int warp = tid >> 5, lane = tid & 31;
    const int g = lane >> 2, tg = lane & 3;
    const int wm = (warp >> 1) * 32, wn = (warp & 1) * 32;

    const int a_row = wm + (lane & 15);
    const int a_col = (lane >> 4) * 4;

    float* Ab = attnP + ((size_t)bh * S_ + qt * 128) * S_;
    const float* Vb = QKV + (size_t)(b * S_) * LDQKV_ + 2048 + h * DEPTH_;
    const float* invb = inv + (size_t)bh * S_ + qt * 128;

    // loader indices: A 128x32 (4 rows/thread), V 32x64 (2 rows/thread)
    const int rL = tid >> 3, kcL = (tid & 7) * 4;
    const int vR = tid >> 4, vC = (tid & 15) * 4;

    float ivA[4];
    #pragma unroll
    for (int i = 0; i < 4; i++) ivA[i] = invb[rL + i * 32];

    float c[2][4][4] = {};
    const int T = (qt + 1) * 4;

    // prologue: stage 0, k0 = 0
    #pragma unroll
    for (int i = 0; i < 4; i++)
        cp16(&As[0][rL + i * 32][kcL], &Ab[(size_t)(rL + i * 32) * S_ + kcL]);
    #pragma unroll
    for (int i = 0; i < 2; i++)
        cp16(&Bs[0][vR + i * 16][vC], &Vb[(size_t)(vR + i * 16) * LDQKV_ + vC]);
    CP_COMMIT();

    for (int t = 0; t < T; t++) {
        if (t + 1 < T) {
            const int k0 = (t + 1) << 5, st = (t + 1) & 1;
            #pragma unroll
            for (int i = 0; i < 4; i++)
                cp16(&As[st][rL + i * 32][kcL], &Ab[(size_t)(rL + i * 32) * S_ + k0 + kcL]);
            #pragma unroll
            for (int i = 0; i < 2; i++)
                cp16(&Bs[st][vR + i * 16][vC], &Vb[(size_t)(k0 + vR + i * 16) * LDQKV_ + vC]);
            CP_COMMIT();
            CP_WAIT1();
        } else {
            CP_WAIT0();
        }
        __syncthreads();
        const int st = t & 1;
        const uint32_t sA = sAbase + (uint32_t)(st * 128 * 36 * 4);
        #pragma unroll
        for (int ks = 0; ks < 32; ks += 8) {
            unsigned a[2][4], bfr[4][2];
            #pragma unroll
            for (int i = 0; i < 2; i++)
                ldsm_x4(a[i][0], a[i][1], a[i][2], a[i][3],
                        sA + (uint32_t)(((a_row + i * 16) * 36 + ks + a_col) * 4));
            #pragma unroll
            for (int j = 0; j < 4; j++) {
                int nB = wn + j * 8;
                bfr[j][0] = Bs[st][ks + tg    ][nB + g];
                bfr[j][1] = Bs[st][ks + tg + 4][nB + g];
            }
            #pragma unroll
            for (int i = 0; i < 2; i++)
                #pragma unroll
                for (int j = 0; j < 4; j++)
                    mma_tf32(c[i][j], a[i][0], a[i][1], a[i][2], a[i][3], bfr[j][0], bfr[j][1]);
        }
        // normalized write-back of this stage's P tile from smem
        #pragma unroll
        for (int i = 0; i < 4; i++) {
            float4 p = *(float4*)&As[st][rL + i * 32][kcL];
            *(float4*)&Ab[(size_t)(rL + i * 32) * S_ + t * 32 + kcL] =
                make_float4(p.x * ivA[i], p.y * ivA[i], p.z * ivA[i], p.w * ivA[i]);
        }
    }

    float ivr[2][2];
    #pragma unroll
    for (int i = 0; i < 2; i++)
        #pragma unroll
        for (int hh = 0; hh < 2; hh++)
            ivr[i][hh] = invb[wm + i * 16 + g + hh * 8];

    #pragma unroll
    for (int i = 0; i < 2; i++)
        #pragma unroll
        for (int j = 0; j < 4; j++) {
            int col = wn + j * 8 + tg * 2;
            #pragma unroll
            for (int hh = 0; hh < 2; hh++) {
                int row = qt * 128 + wm + i * 16 + g + hh * 8;
                int t = b * S_ + row;
                *(float2*)&Ctx[(size_t)t * D_ + h * DEPTH_ + col] =
                    make_float2(roundtf(c[i][j][hh * 2 + 0] * ivr[i][hh]),
                                roundtf(c[i][j][hh * 2 + 1] * ivr[i][hh]));
            }
        }
}

// ---------------- fused residual + LayerNorm ----------------
template <int WRITE_ROUND>
__global__ void ln_residual(const float* __restrict__ a, const float* __restrict__ bb,
                            const float* __restrict__ g, const float* __restrict__ be,
                            float* __restrict__ out, float* __restrict__ outr) {
    const int t = blockIdx.x;
    const int tid = threadIdx.x;
    float4 va = ((const float4*)(a  + (size_t)t * D_))[tid];
    float4 vb = ((const float4*)(bb + (size_t)t * D_))[tid];
    float4 v = make_float4(va.x + vb.x, va.y + vb.y, va.z + vb.z, va.w + vb.w);

    __shared__ float sm[256];
    sm[tid] = v.x + v.y + v.z + v.w; __syncthreads();
    for (int st = 128; st > 0; st >>= 1) { if (tid < st) sm[tid] += sm[tid + st]; __syncthreads(); }
    const float mu = sm[0] * (1.0f / D_);
    __syncthreads();

    float dx = v.x - mu, dy = v.y - mu, dz = v.z - mu, dw = v.w - mu;
    sm[tid] = dx * dx + dy * dy + dz * dz + dw * dw; __syncthreads();
    for (int st = 128; st > 0; st >>= 1) { if (tid < st) sm[tid] += sm[tid + st]; __syncthreads(); }
    const float inv = rsqrtf(sm[0] * (1.0f / D_) + EPS_);

    float4 gg = ((const float4*)g)[tid];
    float4 bz = ((const float4*)be)[tid];
    float4 o = make_float4(dx * inv * gg.x + bz.x, dy * inv * gg.y + bz.y,
                           dz * inv * gg.z + bz.z, dw * inv * gg.w + bz.w);
    ((float4*)(out + (size_t)t * D_))[tid] = o;
    if (WRITE_ROUND) {
        float4 orr = make_float4(roundtf(o.x), roundtf(o.y), roundtf(o.z), roundtf(o.w));
        ((float4*)(outr + (size_t)t * D_))[tid] = orr;
    }
}

// ---------------- launch ----------------
extern "C" void kernel_launch(void* const* d_in, const int* in_sizes, int n_in,
                              void* d_out, int out_size) {
    const float* x  = (const float*)d_in[0];
    const float* Wq = (const float*)d_in[2];  const float* bq = (const float*)d_in[3];
    const float* Wk = (const float*)d_in[4];  const float* bk = (const float*)d_in[5];
    const float* Wv = (const float*)d_in[6];  const float* bv = (const float*)d_in[7];
    const float* Wo = (const float*)d_in[8];  const float* bo = (const float*)d_in[9];
    const float* W1 = (const float*)d_in[10]; const float* b1 = (const float*)d_in[11];
    const float* W2 = (const float*)d_in[12]; const float* b2 = (const float*)d_in[13];
    const float* ln1g = (const float*)d_in[14]; const float* ln1b = (const float*)d_in[15];
    const float* ln2g = (const float*)d_in[16]; const float* ln2b = (const float*)d_in[17];

    float* out  = (float*)d_out;
    float* attn = out + (size_t)NT_ * D_;

    float *qkv, *wcat, *bcat, *ctx, *ao, *x1, *x1r, *h1, *ff2, *xr, *wr, *rs, *inv;
    cudaGetSymbolAddress((void**)&qkv,  g_qkv);
    cudaGetSymbolAddress((void**)&wcat, g_wcat);
    cudaGetSymbolAddress((void**)&bcat, g_bcat);
    cudaGetSymbolAddress((void**)&ctx,  g_ctx);
    cudaGetSymbolAddress((void**)&ao,   g_ao);
    cudaGetSymbolAddress((void**)&x1,   g_x1);
    cudaGetSymbolAddress((void**)&x1r,  g_x1r);
    cudaGetSymbolAddress((void**)&h1,   g_h1);
    cudaGetSymbolAddress((void**)&ff2,  g_ff2);
    cudaGetSymbolAddress((void**)&xr,   g_xr);
    cudaGetSymbolAddress((void**)&wr,   g_wr);
    cudaGetSymbolAddress((void**)&rs,   g_rs);
    cudaGetSymbolAddress((void**)&inv,  g_inv);

    float* WqkvT = wcat;                     // [3072][1024]
    float* WoT   = wr;                       // [1024][1024]
    float* W1T   = wr + 1048576;             // [4096][1024]
    float* W2T   = wr + 5242880;             // [1024][4096]

    const int GEMM_SMEM = 2 * (ASZ_ + BSZ_) * 4;       // 73728
    const int SC_SMEM   = 2 * 128 * 68 * 4;            // 69632
    cudaFuncSetAttribute(gemm_tf32p<0,1>, cudaFuncAttributeMaxDynamicSharedMemorySize, GEMM_SMEM);
    cudaFuncSetAttribute(gemm_tf32p<0,0>, cudaFuncAttributeMaxDynamicSharedMemorySize, GEMM_SMEM);
    cudaFuncSetAttribute(gemm_tf32p<1,1>, cudaFuncAttributeMaxDynamicSharedMemorySize, GEMM_SMEM);
    cudaFuncSetAttribute(attn_scores_exp, cudaFuncAttributeMaxDynamicSharedMemorySize, SC_SMEM);

    dim3 blk(256);
    dim3 tblk(32, 8);

    // transposed + rna-rounded weights
    round_T<<<dim3(32, 32),  tblk>>>(Wq, WqkvT,           1024, 1024);
    round_T<<<dim3(32, 32),  tblk>>>(Wk, WqkvT + 1048576, 1024, 1024);
    round_T<<<dim3(32, 32),  tblk>>>(Wv, WqkvT + 2097152, 1024, 1024);
    round_T<<<dim3(32, 32),  tblk>>>(Wo, WoT,             1024, 1024);
    round_T<<<dim3(128, 32), tblk>>>(W1, W1T,             1024, 4096);
    round_T<<<dim3(32, 128), tblk>>>(W2, W2T,             4096, 1024);
    cudaMemcpyAsync(bcat,        bq, D_ * 4, cudaMemcpyDeviceToDevice);
    cudaMemcpyAsync(bcat + 1024, bk, D_ * 4, cudaMemcpyDeviceToDevice);
    cudaMemcpyAsync(bcat + 2048, bv, D_ * 4, cudaMemcpyDeviceToDevice);
    round_copy<<<4096, blk>>>(x, xr, 1048576);

    // fused QKV: [4096,1024] @ [1024,3072] (Bt = WqkvT [3072][1024])
    dim3 gQKV(LDQKV_ / 128, NT_ / 128);         // (24, 32)
    gemm_tf32p<0,1><<<gQKV, blk, GEMM_SMEM>>>(xr, WqkvT, bcat, qkv, NT_, LDQKV_, D_);

    dim3 gScore(S_ / 128, S_ / 128, B_ * H_);   // (16, 16, 32)
    attn_scores_exp<<<gScore, blk, SC_SMEM>>>(qkv, attn, rs);
    rowsum_inv<<<NROWS_ / 256, blk>>>(rs, inv);

    dim3 gPV(S_ / 128, B_ * H_);                // (16, 32)
    attn_pv_norm<<<gPV, blk>>>(attn, qkv, inv, ctx);

    dim3 gProj(D_ / 128, NT_ / 128);            // (8, 32)
    gemm_tf32p<0,0><<<gProj, blk, GEMM_SMEM>>>(ctx, WoT, bo, ao, NT_, D_, D_);
    ln_residual<1><<<NT_, blk>>>(x, ao, ln1g, ln1b, x1, x1r);

    dim3 gFF1(DFF_ / 128, NT_ / 128);           // (32, 32)
    gemm_tf32p<1,1><<<gFF1, blk, GEMM_SMEM>>>(x1r, W1T, b1, h1, NT_, DFF_, D_);
    gemm_tf32p<0,0><<<gProj, blk, GEMM_SMEM>>>(h1, W2T, b2, ff2, NT_, D_, DFF_);
    ln_residual<0><<<NT_, blk>>>(x1, ff2, ln2g, ln2b, out, nullptr);
}